// round 11
// baseline (speedup 1.0000x reference)
#include <cuda_runtime.h>
#include <cuda_bf16.h>
#include <mma.h>
#include <cuda_pipeline.h>
#include <math_constants.h>

using namespace nvcuda;

#define BB 2
#define SS 2048
#define DD 1024
#define HH 16
#define DHD 64
#define MTOT (BB*SS)   // 4096
#define COUT 512

typedef __nv_bfloat16 bf16;

// ---------------- scratch (device globals; no allocation allowed) -------------
__device__ float g_km[BB*HH*SS*DHD];   // (1-g)*kh   (head layout)
__device__ float g_kc[BB*HH*SS*DHD];   // g*(conv+bias) (head layout)

// bf16 hi/lo splits (GEMM inputs)
__device__ bf16 g_qh[MTOT*DD],  g_ql[MTOT*DD];
__device__ bf16 g_kh[MTOT*DD],  g_kl[MTOT*DD];
__device__ bf16 g_vh[MTOT*DD],  g_vl[MTOT*DD];
__device__ bf16 g_aoh[MTOT*DD], g_aol[MTOT*DD];
__device__ bf16 g_Wqh[DD*DD], g_Wql[DD*DD];
__device__ bf16 g_Wkh[DD*DD], g_Wkl[DD*DD];
__device__ bf16 g_Wvh[DD*DD], g_Wvl[DD*DD];
__device__ bf16 g_Woh[DD*DD], g_Wol[DD*DD];
__device__ bf16 g_wt0h[3*COUT*DD], g_wt0l[3*COUT*DD];   // [t][co][ci]
__device__ bf16 g_wt1h[5*COUT*DD], g_wt1l[5*COUT*DD];

// bf16 hi/lo, head layout [B,H,S,DH] (attention inputs)
__device__ bf16 g_qhh[BB*HH*SS*DHD], g_qhl[BB*HH*SS*DHD];
__device__ bf16 g_kmh[BB*HH*SS*DHD], g_kml[BB*HH*SS*DHD];
__device__ bf16 g_vhh[BB*HH*SS*DHD], g_vhl[BB*HH*SS*DHD];

// packed mask bits: [B][S][S/32] words
__device__ unsigned int g_mbits[BB*SS*(SS/32)];

__device__ __forceinline__ float sigm(float x){ return 1.0f/(1.0f+__expf(-x)); }

__device__ __forceinline__ void split4(float4 f, uint2& hv, uint2& lv){
    float fv[4] = {f.x, f.y, f.z, f.w};
    unsigned int hw[4], lw[4];
    #pragma unroll
    for (int j=0;j<4;j++){
        bf16 h = __float2bfloat16(fv[j]);
        bf16 l = __float2bfloat16(fv[j] - __bfloat162float(h));
        hw[j] = (unsigned int)__bfloat16_as_ushort(h);
        lw[j] = (unsigned int)__bfloat16_as_ushort(l);
    }
    hv = make_uint2(hw[0] | (hw[1]<<16), hw[2] | (hw[3]<<16));
    lv = make_uint2(lw[0] | (lw[1]<<16), lw[2] | (lw[3]<<16));
}

// ---------------- ONE fused prep kernel ----------------------------------------
// ranges: [0,6144) qkv split, [6144,8192) W split, [8192,18432) conv-wt,
//         [18432,51200) mask bits
#define NBIG4 (MTOT*DD/4)
#define NBIG8 (NBIG4/2)
#define NW8   (DD*DD/8)

__global__ void prep_all(const float* __restrict__ q, const float* __restrict__ k,
                         const float* __restrict__ v,
                         const float* __restrict__ Wq, const float* __restrict__ Wk,
                         const float* __restrict__ Wv, const float* __restrict__ Wo,
                         const float* __restrict__ w0, const float* __restrict__ w1,
                         const int* __restrict__ mask){
    int bid = blockIdx.x;
    if (bid < 6144){
        int i = bid*256 + threadIdx.x;
        if (i >= 3*NBIG8) return;
        int sel = i / NBIG8, j = (i - sel*NBIG8)*2;
        const float4* s4; uint2 *hi, *lo;
        if (sel==0){ s4=(const float4*)q; hi=(uint2*)g_qh; lo=(uint2*)g_ql; }
        else if (sel==1){ s4=(const float4*)k; hi=(uint2*)g_kh; lo=(uint2*)g_kl; }
        else { s4=(const float4*)v; hi=(uint2*)g_vh; lo=(uint2*)g_vl; }
        float4 f0 = s4[j], f1 = s4[j+1];
        uint2 hv, lv;
        split4(f0, hv, lv); hi[j]=hv;   lo[j]=lv;
        split4(f1, hv, lv); hi[j+1]=hv; lo[j+1]=lv;
    } else if (bid < 8192){
        int i = (bid-6144)*256 + threadIdx.x;
        if (i >= 4*NW8) return;
        int sel = i / NW8, j = (i - sel*NW8)*2;
        const float4* s4; uint2 *hi, *lo;
        if (sel==0){ s4=(const float4*)Wq; hi=(uint2*)g_Wqh; lo=(uint2*)g_Wql; }
        else if (sel==1){ s4=(const float4*)Wk; hi=(uint2*)g_Wkh; lo=(uint2*)g_Wkl; }
        else if (sel==2){ s4=(const float4*)Wv; hi=(uint2*)g_Wvh; lo=(uint2*)g_Wvl; }
        else { s4=(const float4*)Wo; hi=(uint2*)g_Woh; lo=(uint2*)g_Wol; }
        float4 f0 = s4[j], f1 = s4[j+1];
        uint2 hv, lv;
        split4(f0, hv, lv); hi[j]=hv;   lo[j]=lv;
        split4(f1, hv, lv); hi[j+1]=hv; lo[j+1]=lv;
    } else if (bid < 18432){
        int idx = (bid-8192)*256 + threadIdx.x;
        const int tot0 = 3*COUT*DD;
        const int tot1 = 5*COUT*DD;
        if (idx < tot0){
            int t = idx/(COUT*DD); int r = idx%(COUT*DD);
            int co = r/DD, ci = r%DD;
            float vv = w0[(co*DD+ci)*3 + t];
            bf16 h = __float2bfloat16(vv);
            g_wt0h[idx] = h;
            g_wt0l[idx] = __float2bfloat16(vv - __bfloat162float(h));
        }
        if (idx < tot1){
            int t = idx/(COUT*DD); int r = idx%(COUT*DD);
            int co = r/DD, ci = r%DD;
            float vv = w1[(co*DD+ci)*5 + t];
            bf16 h = __float2bfloat16(vv);
            g_wt1h[idx] = h;
            g_wt1l[idx] = __float2bfloat16(vv - __bfloat162float(h));
        }
    } else {
        int i = (bid-18432)*256 + threadIdx.x;   // one thread per mask element
        unsigned int b = __ballot_sync(0xffffffffu, mask[i] != 0);
        if ((threadIdx.x & 31) == 0) g_mbits[i >> 5] = b;
    }
}

// km = g_km + g_kc, split to head-layout hi/lo (2 float4/thread)
__global__ void cvt_km(int n8){
    int i0 = (blockIdx.x*blockDim.x + threadIdx.x);
    if (i0 >= n8) return;
    int j = i0*2;
    #pragma unroll
    for (int t=0;t<2;t++){
        float4 a = ((const float4*)g_km)[j+t];
        float4 b = ((const float4*)g_kc)[j+t];
        a.x += b.x; a.y += b.y; a.z += b.z; a.w += b.w;
        uint2 hv, lv; split4(a, hv, lv);
        ((uint2*)g_kmh)[j+t]=hv; ((uint2*)g_kml)[j+t]=lv;
    }
}

// ---------------- fused tensor-core bf16x3 GEMM (4 warps, 64x64 warp tiles) -----
#define BKS 16
#define SST 24           // smem row stride in bf16 elems (16 data + 8 pad)
#define TILEE 3072       // one 128-row array: 128*SST elems
#define STGE 12288       // 4 arrays per stage (elems)
#define NSTG 3
#define SMEM_BYTES 73728 // 3 stages * 24576B

// 128 threads: each thread loads one full row (32B) per array
__device__ __forceinline__ void cp_stage_rt(int mode, bf16* smem, int slot, int k0,
                                            int m0, int n0, int tid){
    const bf16 *Ah, *Al, *Bh, *Bl;
    if (mode==0){ Ah=g_qh; Al=g_ql; Bh=g_Wqh; Bl=g_Wql; }
    else if (mode==1){ Ah=g_kh; Al=g_kl; Bh=g_Wkh; Bl=g_Wkl; }
    else if (mode==3){ Ah=g_vh; Al=g_vl; Bh=g_Wvh; Bl=g_Wvl; }
    else if (mode==4){ Ah=g_kh; Al=g_kl; Bh=g_wt0h; Bl=g_wt0l; }
    else { Ah=g_kh; Al=g_kl; Bh=g_wt1h; Bl=g_wt1l; }

    const int row = tid;   // 0..127
    bf16* pA = smem + slot*STGE + row*SST;

    if (mode<=3){
        size_t off = (size_t)(m0+row)*DD + k0;
        __pipeline_memcpy_async(pA,           Ah+off,   16);
        __pipeline_memcpy_async(pA+8,         Ah+off+8, 16);
        __pipeline_memcpy_async(pA+TILEE,     Al+off,   16);
        __pipeline_memcpy_async(pA+TILEE+8,   Al+off+8, 16);
        size_t offb = (size_t)(n0+row)*DD + k0;
        __pipeline_memcpy_async(pA+2*TILEE,   Bh+offb,   16);
        __pipeline_memcpy_async(pA+2*TILEE+8, Bh+offb+8, 16);
        __pipeline_memcpy_async(pA+3*TILEE,   Bl+offb,   16);
        __pipeline_memcpy_async(pA+3*TILEE+8, Bl+offb+8, 16);
    } else {
        const int pad = (mode==4)?1:2;
        int t   = k0 >> 10;
        int ci0 = k0 & 1023;
        int m   = m0 + row;
        int bidx = m >> 11;
        int s2  = (m & 2047) + t - pad;
        bool ok = (s2 >= 0 && s2 < SS);
        size_t off = ok ? ((size_t)(bidx*SS + s2)*DD + ci0) : 0;
        size_t zf  = ok ? 0 : 16;
        __pipeline_memcpy_async(pA,         Ah+off,   16, zf);
        __pipeline_memcpy_async(pA+8,       Ah+off+8, 16, zf);
        __pipeline_memcpy_async(pA+TILEE,   Al+off,   16, zf);
        __pipeline_memcpy_async(pA+TILEE+8, Al+off+8, 16, zf);
        size_t offb = ((size_t)t*COUT + (n0+row))*DD + ci0;
        __pipeline_memcpy_async(pA+2*TILEE,   Bh+offb,   16);
        __pipeline_memcpy_async(pA+2*TILEE+8, Bh+offb+8, 16);
        __pipeline_memcpy_async(pA+3*TILEE,   Bl+offb,   16);
        __pipeline_memcpy_async(pA+3*TILEE+8, Bl+offb+8, 16);
    }
}

__global__ __launch_bounds__(128,2) void mma_gemm_fused(
        const float* __restrict__ gate, const float* __restrict__ cb0,
        const float* __restrict__ cb1){
    extern __shared__ __align__(16) bf16 smem[];
    const int tid  = threadIdx.x;
    const int wid  = tid >> 5, lane = tid & 31;
    const int wm   = wid >> 1, wn = wid & 1;     // warp grid 2x2, warp tile 64x64

    // block -> (mode, tile); heaviest blocks first
    int bid = blockIdx.x;
    int mode, r;
    if (bid < 128)      { mode=5; r=bid; }
    else if (bid < 256) { mode=4; r=bid-128; }
    else if (bid < 512) { mode=1; r=bid-256; }
    else if (bid < 768) { mode=0; r=bid-512; }
    else                { mode=3; r=bid-768; }
    int m0, n0;
    if (mode>=4){ n0=(r&3)*128; m0=(r>>2)*128; }
    else        { n0=(r&7)*128; m0=(r>>3)*128; }
    const int STEPS = (mode==5) ? 320 : (mode==4) ? 192 : 64;

    wmma::fragment<wmma::accumulator,16,16,16,float> facc[4][4];
    #pragma unroll
    for (int i=0;i<4;i++)
        #pragma unroll
        for (int j=0;j<4;j++) wmma::fill_fragment(facc[i][j], 0.0f);

    cp_stage_rt(mode, smem, 0, 0,   m0, n0, tid); __pipeline_commit();
    cp_stage_rt(mode, smem, 1, BKS, m0, n0, tid); __pipeline_commit();

    for (int s=0; s<STEPS; s++){
        __pipeline_wait_prior(1);
        __syncthreads();

        const bf16* sAh = smem + (s%NSTG)*STGE;
        const bf16* sAl = sAh + TILEE;
        const bf16* sBh = sAh + 2*TILEE;
        const bf16* sBl = sAh + 3*TILEE;

        wmma::fragment<wmma::matrix_a,16,16,16,bf16,wmma::row_major> fah[4], fal[4];
        #pragma unroll
        for (int i=0;i<4;i++){
            wmma::load_matrix_sync(fah[i], sAh + (wm*64 + i*16)*SST, SST);
            wmma::load_matrix_sync(fal[i], sAl + (wm*64 + i*16)*SST, SST);
        }
        #pragma unroll
        for (int j=0;j<4;j++){
            wmma::fragment<wmma::matrix_b,16,16,16,bf16,wmma::col_major> fbh, fbl;
            wmma::load_matrix_sync(fbh, sBh + (wn*64 + j*16)*SST, SST);
            wmma::load_matrix_sync(fbl, sBl + (wn*64 + j*16)*SST, SST);
            #pragma unroll
            for (int i=0;i<4;i++){
                wmma::mma_sync(facc[i][j], fah[i], fbh, facc[i][j]);
                wmma::mma_sync(facc[i][j], fah[i], fbl, facc[i][j]);
                wmma::mma_sync(facc[i][j], fal[i], fbh, facc[i][j]);
            }
        }
        if (s+2 < STEPS) cp_stage_rt(mode, smem, (s+2)%NSTG, (s+2)*BKS, m0, n0, tid);
        __pipeline_commit();
    }
    __syncthreads();

    // ---- epilogue: per-warp 1KB scratch chunks ----
    float* scr = (float*)smem + wid*256;   // 16x16 per warp
    #pragma unroll
    for (int i=0;i<4;i++){
        #pragma unroll
        for (int j=0;j<4;j++){
            wmma::store_matrix_sync(scr, facc[i][j], 16, wmma::mem_row_major);
            __syncwarp();
            #pragma unroll
            for (int t=0;t<8;t++){
                int e = lane + t*32;
                int row = e >> 4, col = e & 15;
                float val = scr[e];
                int gm = m0 + wm*64 + i*16 + row;
                int gn = n0 + wn*64 + j*16 + col;
                int bidx = gm>>11, ss2 = gm&2047;
                if (mode==0 || mode==3){
                    int hh2 = gn>>6, d = gn&63;
                    size_t idx = (((size_t)bidx*HH+hh2)*SS+ss2)*DHD + d;
                    bf16 hv = __float2bfloat16(val);
                    bf16 lv = __float2bfloat16(val - __bfloat162float(hv));
                    if (mode==0){ g_qhh[idx]=hv; g_qhl[idx]=lv; }
                    else        { g_vhh[idx]=hv; g_vhl[idx]=lv; }
                } else if (mode==1){
                    int hh2 = gn>>6, d = gn&63;
                    float sc = 1.0f - sigm(gate[hh2]);
                    g_km[(((size_t)bidx*HH+hh2)*SS+ss2)*DHD + d] = val*sc;
                } else {
                    const int branch = (mode==5) ? 1 : 0;
                    const float* bias = branch ? cb1 : cb0;
                    int gc = branch*COUT + gn;
                    int hh2 = gc>>6, d = gc&63;
                    float g = sigm(gate[hh2]);
                    g_kc[(((size_t)bidx*HH+hh2)*SS+ss2)*DHD + d] = g*(val + bias[gn]);
                }
            }
            __syncwarp();
        }
    }
}

// ---------------- out-projection GEMM (after attention) -------------------------
__device__ __forceinline__ void cp_out(bf16* smem, int slot, int k0,
                                       int m0, int n0, int tid){
    const int row = tid;
    bf16* pA = smem + slot*STGE + row*SST;
    size_t off  = (size_t)(m0+row)*DD + k0;
    size_t offb = (size_t)(n0+row)*DD + k0;
    __pipeline_memcpy_async(pA,           g_aoh+off,   16);
    __pipeline_memcpy_async(pA+8,         g_aoh+off+8, 16);
    __pipeline_memcpy_async(pA+TILEE,     g_aol+off,   16);
    __pipeline_memcpy_async(pA+TILEE+8,   g_aol+off+8, 16);
    __pipeline_memcpy_async(pA+2*TILEE,   g_Woh+offb,   16);
    __pipeline_memcpy_async(pA+2*TILEE+8, g_Woh+offb+8, 16);
    __pipeline_memcpy_async(pA+3*TILEE,   g_Wol+offb,   16);
    __pipeline_memcpy_async(pA+3*TILEE+8, g_Wol+offb+8, 16);
}

__global__ __launch_bounds__(128,2) void mma_gemm_out(
        float* __restrict__ dstp, const float* __restrict__ bo){
    extern __shared__ __align__(16) bf16 smem[];
    const int tid  = threadIdx.x;
    const int wid  = tid >> 5, lane = tid & 31;
    const int wm   = wid >> 1, wn = wid & 1;
    const int m0   = blockIdx.y*128;
    const int n0   = blockIdx.x*128;
    const int STEPS = DD/BKS;

    wmma::fragment<wmma::accumulator,16,16,16,float> facc[4][4];
    #pragma unroll
    for (int i=0;i<4;i++)
        #pragma unroll
        for (int j=0;j<4;j++) wmma::fill_fragment(facc[i][j], 0.0f);

    cp_out(smem, 0, 0,   m0, n0, tid); __pipeline_commit();
    cp_out(smem, 1, BKS, m0, n0, tid); __pipeline_commit();

    for (int s=0; s<STEPS; s++){
        __pipeline_wait_prior(1);
        __syncthreads();

        const bf16* sAh = smem + (s%NSTG)*STGE;
        const bf16* sAl = sAh + TILEE;
        const bf16* sBh = sAh + 2*TILEE;
        const bf16* sBl = sAh + 3*TILEE;

        wmma::fragment<wmma::matrix_a,16,16,16,bf16,wmma::row_major> fah[4], fal[4];
        #pragma unroll
        for (int i=0;i<4;i++){
            wmma::load_matrix_sync(fah[i], sAh + (wm*64 + i*16)*SST, SST);
            wmma::load_matrix_sync(fal[i], sAl + (wm*64 + i*16)*SST, SST);
        }
        #pragma unroll
        for (int j=0;j<4;j++){
            wmma::fragment<wmma::matrix_b,16,16,16,bf16,wmma::col_major> fbh, fbl;
            wmma::load_matrix_sync(fbh, sBh + (wn*64 + j*16)*SST, SST);
            wmma::load_matrix_sync(fbl, sBl + (wn*64 + j*16)*SST, SST);
            #pragma unroll
            for (int i=0;i<4;i++){
                wmma::mma_sync(facc[i][j], fah[i], fbh, facc[i][j]);
                wmma::mma_sync(facc[i][j], fah[i], fbl, facc[i][j]);
                wmma::mma_sync(facc[i][j], fal[i], fbh, facc[i][j]);
            }
        }
        if (s+2 < STEPS) cp_out(smem, (s+2)%NSTG, (s+2)*BKS, m0, n0, tid);
        __pipeline_commit();
    }
    __syncthreads();

    float* scr = (float*)smem + wid*256;
    #pragma unroll
    for (int i=0;i<4;i++){
        #pragma unroll
        for (int j=0;j<4;j++){
            wmma::store_matrix_sync(scr, facc[i][j], 16, wmma::mem_row_major);
            __syncwarp();
            #pragma unroll
            for (int t=0;t<8;t++){
                int e = lane + t*32;
                int row2 = e >> 4, col = e & 15;
                int gm = m0 + wm*64 + i*16 + row2;
                int gn = n0 + wn*64 + j*16 + col;
                dstp[(size_t)gm*DD + gn] = scr[e] + bo[gn];
            }
            __syncwarp();
        }
    }
}

// ---------------- flash attention: in-register softmax, cp.async 3-stage KV ----
#define FQT 128
#define FKT 64
#define FST 72       // bf16 row stride (64 data + 8 pad)
#define KVB 9216     // one 64x72 bf16 array in bytes
#define BUFBY 36864  // Kh,Kl,Vh,Vl per stage
#define O_P 110592   // after 3 KV stages; Ph (18432B) + Pl (18432B); also Q staging
#define FSM 147456

__device__ __forceinline__ void cp_kv(unsigned char* fsm, int slot, size_t base,
                                      int k0, int tid){
    #pragma unroll
    for (int i=0;i<8;i++){
        int idx = tid + i*256;
        int arr = idx >> 9, e = idx & 511;
        int row = e >> 3, c = (e & 7)*8;
        const bf16* src = g_kmh;
        if (arr==1) src = g_kml;
        if (arr==2) src = g_vhh;
        if (arr==3) src = g_vhl;
        __pipeline_memcpy_async((bf16*)(fsm + slot*BUFBY + arr*KVB) + row*FST + c,
                                src + base + (size_t)(k0+row)*DHD + c, 16);
    }
}
__device__ __forceinline__ void st_pair(bf16* hp, bf16* lp, int off, float a, float b){
    bf16 ha = __float2bfloat16(a);
    bf16 hb = __float2bfloat16(b);
    __nv_bfloat162 hv; hv.x = ha; hv.y = hb;
    __nv_bfloat162 lv;
    lv.x = __float2bfloat16(a - __bfloat162float(ha));
    lv.y = __float2bfloat16(b - __bfloat162float(hb));
    *(__nv_bfloat162*)(hp + off) = hv;
    *(__nv_bfloat162*)(lp + off) = lv;
}

__global__ __launch_bounds__(256,1) void flash_wmma(int dummy){
    extern __shared__ __align__(16) unsigned char fsm[];
    const int tid = threadIdx.x;
    const int w = tid >> 5, lane = tid & 31;
    const int bh = blockIdx.y;
    const int b = bh >> 4, h = bh & 15;
    const int q0 = blockIdx.x*FQT;
    const size_t base = (size_t)bh*SS*DHD;
    const int NI = SS/FKT;   // 32

    bf16* Ph = (bf16*)(fsm + O_P);
    bf16* Pl = (bf16*)(fsm + O_P + 18432);

    #pragma unroll
    for (int i=0;i<4;i++){
        int idx = tid + i*256;
        int row = idx >> 3, c = (idx & 7)*8;
        *(uint4*)(Ph + row*FST + c) = *(const uint4*)(g_qhh + base + (size_t)(q0+row)*DHD + c);
        *(uint4*)(Pl + row*FST + c) = *(const uint4*)(g_qhl + base + (size_t)(q0+row)*DHD + c);
    }
    cp_kv(fsm, 0, base, 0,   tid); __pipeline_commit();
    cp_kv(fsm, 1, base, FKT, tid); __pipeline_commit();
    __syncthreads();

    wmma::fragment<wmma::matrix_a,16,16,16,bf16,wmma::row_major> qah[4], qal[4];
    #pragma unroll
    for (int kk=0;kk<4;kk++){
        wmma::load_matrix_sync(qah[kk], Ph + (w*16)*FST + kk*16, FST);
        wmma::load_matrix_sync(qal[kk], Pl + (w*16)*FST + kk*16, FST);
    }

    wmma::fragment<wmma::accumulator,16,16,16,float> oacc[4];
    #pragma unroll
    for (int j=0;j<4;j++) wmma::fill_fragment(oacc[j], 0.0f);

    const int r0 = lane >> 2;
    const int grow0 = q0 + w*16 + r0;
    float mr0 = -CUDART_INF_F, mr1 = -CUDART_INF_F;
    float l0 = 0.0f, l1 = 0.0f;
    const float scl = 0.125f;

    for (int kb=0; kb<NI; kb++){
        __pipeline_wait_prior(1);
        __syncthreads();

        const int cur = kb % 3;
        bf16* Kh = (bf16*)(fsm + cur*BUFBY);
        bf16* Kl = (bf16*)(fsm + cur*BUFBY + KVB);
        bf16* Vh = (bf16*)(fsm + cur*BUFBY + 2*KVB);
        bf16* Vl = (bf16*)(fsm + cur*BUFBY + 3*KVB);

        wmma::fragment<wmma::accumulator,16,16,16,float> sacc[4];
        #pragma unroll
        for (int j=0;j<4;j++) wmma::fill_fragment(sacc[j], 0.0f);

        #pragma unroll
        for (int kk=0;kk<4;kk++){
            #pragma unroll
            for (int j=0;j<4;j++){
                wmma::fragment<wmma::matrix_b,16,16,16,bf16,wmma::col_major> kbh, kbl;
                wmma::load_matrix_sync(kbh, Kh + (j*16)*FST + kk*16, FST);
                wmma::load_matrix_sync(kbl, Kl + (j*16)*FST + kk*16, FST);
                wmma::mma_sync(sacc[j], qah[kk], kbh, sacc[j]);
                wmma::mma_sync(sacc[j], qah[kk], kbl, sacc[j]);
                wmma::mma_sync(sacc[j], qal[kk], kbh, sacc[j]);
            }
        }

        uint2 w0u = *(const uint2*)(g_mbits + ((size_t)b*SS + grow0)*(SS/32) + kb*2);
        uint2 w1u = *(const uint2*)(g_mbits + ((size_t)b*SS + grow0 + 8)*(SS/32) + kb*2);
        unsigned long long mb0 = ((unsigned long long)w0u.y << 32) | w0u.x;
        unsigned long long mb1 = ((unsigned long long)w1u.y << 32) | w1u.x;

        float rm0 = -CUDART_INF_F, rm1 = -CUDART_INF_F;
        #pragma unroll
        for (int j=0;j<4;j++){
            float* x = sacc[j].x;
            int c0 = j*16 + (lane&3)*2;
            x[0] = ((mb0 >> c0)     & 1) ? x[0]*scl : -1e9f;
            x[1] = ((mb0 >> (c0+1)) & 1) ? x[1]*scl : -1e9f;
            x[4] = ((mb0 >> (c0+8)) & 1) ? x[4]*scl : -1e9f;
            x[5] = ((mb0 >> (c0+9)) & 1) ? x[5]*scl : -1e9f;
            x[2] = ((mb1 >> c0)     & 1) ? x[2]*scl : -1e9f;
            x[3] = ((mb1 >> (c0+1)) & 1) ? x[3]*scl : -1e9f;
            x[6] = ((mb1 >> (c0+8)) & 1) ? x[6]*scl : -1e9f;
            x[7] = ((mb1 >> (c0+9)) & 1) ? x[7]*scl : -1e9f;
            rm0 = fmaxf(rm0, fmaxf(fmaxf(x[0],x[1]), fmaxf(x[4],x[5])));
            rm1 = fmaxf(rm1, fmaxf(fmaxf(x[2],x[3]), fmaxf(x[6],x[7])));
        }
        rm0 = fmaxf(rm0, __shfl_xor_sync(0xffffffffu, rm0, 1));
        rm0 = fmaxf(rm0, __shfl_xor_sync(0xffffffffu, rm0, 2));
        rm1 = fmaxf(rm1, __shfl_xor_sync(0xffffffffu, rm1, 1));
        rm1 = fmaxf(rm1, __shfl_xor_sync(0xffffffffu, rm1, 2));

        float mn0 = fmaxf(mr0, rm0), mn1 = fmaxf(mr1, rm1);
        float cr0 = __expf(mr0 - mn0), cr1 = __expf(mr1 - mn1);

        float ps0 = 0.0f, ps1 = 0.0f;
        const int lr0 = w*16 + r0;
        #pragma unroll
        for (int j=0;j<4;j++){
            float* x = sacc[j].x;
            int c0 = j*16 + (lane&3)*2;
            float p00 = __expf(x[0]-mn0), p01 = __expf(x[1]-mn0);
            float p08 = __expf(x[4]-mn0), p09 = __expf(x[5]-mn0);
            float p10 = __expf(x[2]-mn1), p11 = __expf(x[3]-mn1);
            float p18 = __expf(x[6]-mn1), p19 = __expf(x[7]-mn1);
            ps0 += (p00+p01) + (p08+p09);
            ps1 += (p10+p11) + (p18+p19);
            st_pair(Ph, Pl, lr0*FST + c0,       p00, p01);
            st_pair(Ph, Pl, lr0*FST + c0 + 8,   p08, p09);
            st_pair(Ph, Pl, (lr0+8)*FST + c0,   p10, p11);
            st_pair(Ph, Pl, (lr0+8)*FST + c0+8, p18, p19);
        }
        ps0 += __shfl_xor_sync(0xffffffffu, ps0, 1);
        ps0 += __shfl_xor_sync(0xffffffffu, ps0, 2);
        ps1 += __shfl_xor_sync(0xffffffffu, ps1, 1);
        ps1 += __shfl_xor_sync(0xffffffffu, ps1, 2);

        l0 = l0*cr0 + ps0;  l1 = l1*cr1 + ps1;
        mr0 = mn0;          mr1 = mn1;

        #pragma unroll
        for (int j=0;j<4;j++){
            float* x = oacc[j].x;
            x[0]*=cr0; x[1]*=cr0; x[4]*=cr0; x[5]*=cr0;
            x[2]*=cr1; x[3]*=cr1; x[6]*=cr1; x[7]*=cr1;
        }
        __syncwarp();

        #pragma unroll
        for (int kk=0;kk<4;kk++){
            wmma::fragment<wmma::matrix_a,16,16,16,bf16,wmma::row_major> pah, pal;
            wmma::load_matrix_sync(pah, Ph + (w*16)*FST + kk*16, FST);
            wmma::load_matrix_sync(pal, Pl + (w*16)*FST + kk*16, FST);
            #pragma unroll
            for (int j=0;j<4;j++){
                wmma::fragment<wmma::matrix_b,16,16,16,bf16,wmma::row_major> vbh, vbl;
                wmma::load_matrix_sync(vbh, Vh + (kk*16)*FST + j*16, FST);
                wmma::load_matrix_sync(vbl, Vl + (kk*16)*FST + j*16, FST);
                wmma::mma_sync(oacc[j], pah, vbh, oacc[j]);
                wmma::mma_sync(oacc[j], pah, vbl, oacc[j]);
                wmma::mma_sync(oacc[j], pal, vbh, oacc[j]);
            }
        }

        if (kb+2 < NI) cp_kv(fsm, (kb+2)%3, base, (kb+2)*FKT, tid);
        __pipeline_commit();
    }

    float inv0 = 1.0f / l0, inv1 = 1.0f / l1;
    int gr0 = q0 + w*16 + r0, gr1 = gr0 + 8;
    size_t ro0 = ((size_t)b*SS + gr0)*DD + h*DHD;
    size_t ro1 = ((size_t)b*SS + gr1)*DD + h*DHD;
    #pragma unroll
    for (int j=0;j<4;j++){
        float* x = oacc[j].x;
        int c0 = j*16 + (lane&3)*2;
        st_pair(g_aoh + ro0, g_aol + ro0, c0,     x[0]*inv0, x[1]*inv0);
        st_pair(g_aoh + ro0, g_aol + ro0, c0 + 8, x[4]*inv0, x[5]*inv0);
        st_pair(g_aoh + ro1, g_aol + ro1, c0,     x[2]*inv1, x[3]*inv1);
        st_pair(g_aoh + ro1, g_aol + ro1, c0 + 8, x[6]*inv1, x[7]*inv1);
    }
}

// ---------------- launch ------------------------------------------------------
extern "C" void kernel_launch(void* const* d_in, const int* in_sizes, int n_in,
                              void* d_out, int out_size){
    const float* q    = (const float*)d_in[0];
    const float* k    = (const float*)d_in[1];
    const float* v    = (const float*)d_in[2];
    const int*   mask = (const int*)  d_in[3];
    const float* Wq   = (const float*)d_in[4];
    const float* Wk   = (const float*)d_in[5];
    const float* Wv   = (const float*)d_in[6];
    const float* Wo   = (const float*)d_in[7];
    const float* bo   = (const float*)d_in[8];
    const float* cw0  = (const float*)d_in[9];
    const float* cb0  = (const float*)d_in[10];
    const float* cw1  = (const float*)d_in[11];
    const float* cb1  = (const float*)d_in[12];
    const float* gate = (const float*)d_in[13];
    float* out = (float*)d_out;

    prep_all<<<51200,256>>>(q, k, v, Wq, Wk, Wv, Wo, cw0, cw1, mask);

    cudaFuncSetAttribute(mma_gemm_fused, cudaFuncAttributeMaxDynamicSharedMemorySize, SMEM_BYTES);
    cudaFuncSetAttribute(mma_gemm_out,   cudaFuncAttributeMaxDynamicSharedMemorySize, SMEM_BYTES);
    cudaFuncSetAttribute(flash_wmma,     cudaFuncAttributeMaxDynamicSharedMemorySize, FSM);

    mma_gemm_fused<<<1024,128,SMEM_BYTES>>>(gate, cb0, cb1);

    cvt_km<<<(NBIG8+255)/256,256>>>(NBIG8);   // (g_km + g_kc) -> kmh/kml

    flash_wmma<<<dim3(SS/FQT, BB*HH), 256, FSM>>>(0);

    mma_gemm_out<<<dim3(DD/128, MTOT/128),128,SMEM_BYTES>>>(out, bo);
}

// round 13
// speedup vs baseline: 1.2559x; 1.2559x over previous
#include <cuda_runtime.h>
#include <cuda_bf16.h>
#include <mma.h>
#include <cuda_pipeline.h>
#include <math_constants.h>

using namespace nvcuda;

#define BB 2
#define SS 2048
#define DD 1024
#define HH 16
#define DHD 64
#define MTOT (BB*SS)   // 4096
#define COUT 512

typedef __nv_bfloat16 bf16;

// ---------------- scratch (device globals; no allocation allowed) -------------
__device__ float g_km[BB*HH*SS*DHD];   // (1-g)*kh   (head layout)
__device__ float g_kc[BB*HH*SS*DHD];   // g*(conv+bias) (head layout)

// bf16 hi/lo splits (GEMM inputs)
__device__ bf16 g_qh[MTOT*DD],  g_ql[MTOT*DD];
__device__ bf16 g_kh[MTOT*DD],  g_kl[MTOT*DD];
__device__ bf16 g_vh[MTOT*DD],  g_vl[MTOT*DD];
__device__ bf16 g_aoh[MTOT*DD], g_aol[MTOT*DD];
__device__ bf16 g_Wqh[DD*DD], g_Wql[DD*DD];
__device__ bf16 g_Wkh[DD*DD], g_Wkl[DD*DD];
__device__ bf16 g_Wvh[DD*DD], g_Wvl[DD*DD];
__device__ bf16 g_Woh[DD*DD], g_Wol[DD*DD];
__device__ bf16 g_wt0h[3*COUT*DD], g_wt0l[3*COUT*DD];   // [t][co][ci]
__device__ bf16 g_wt1h[5*COUT*DD], g_wt1l[5*COUT*DD];

// bf16 hi/lo, head layout [B,H,S,DH] (attention inputs)
__device__ bf16 g_qhh[BB*HH*SS*DHD], g_qhl[BB*HH*SS*DHD];
__device__ bf16 g_kmh[BB*HH*SS*DHD], g_kml[BB*HH*SS*DHD];
__device__ bf16 g_vhh[BB*HH*SS*DHD], g_vhl[BB*HH*SS*DHD];

// packed mask bits: [B][S][S/32] words
__device__ unsigned int g_mbits[BB*SS*(SS/32)];

__device__ __forceinline__ float sigm(float x){ return 1.0f/(1.0f+__expf(-x)); }

__device__ __forceinline__ void split4(float4 f, uint2& hv, uint2& lv){
    float fv[4] = {f.x, f.y, f.z, f.w};
    unsigned int hw[4], lw[4];
    #pragma unroll
    for (int j=0;j<4;j++){
        bf16 h = __float2bfloat16(fv[j]);
        bf16 l = __float2bfloat16(fv[j] - __bfloat162float(h));
        hw[j] = (unsigned int)__bfloat16_as_ushort(h);
        lw[j] = (unsigned int)__bfloat16_as_ushort(l);
    }
    hv = make_uint2(hw[0] | (hw[1]<<16), hw[2] | (hw[3]<<16));
    lv = make_uint2(lw[0] | (lw[1]<<16), lw[2] | (lw[3]<<16));
}

// ---------------- ONE fused prep kernel ----------------------------------------
#define NBIG4 (MTOT*DD/4)
#define NBIG8 (NBIG4/2)
#define NW8   (DD*DD/8)

__global__ void prep_all(const float* __restrict__ q, const float* __restrict__ k,
                         const float* __restrict__ v,
                         const float* __restrict__ Wq, const float* __restrict__ Wk,
                         const float* __restrict__ Wv, const float* __restrict__ Wo,
                         const float* __restrict__ w0, const float* __restrict__ w1,
                         const int* __restrict__ mask){
    int bid = blockIdx.x;
    if (bid < 6144){
        int i = bid*256 + threadIdx.x;
        if (i >= 3*NBIG8) return;
        int sel = i / NBIG8, j = (i - sel*NBIG8)*2;
        const float4* s4; uint2 *hi, *lo;
        if (sel==0){ s4=(const float4*)q; hi=(uint2*)g_qh; lo=(uint2*)g_ql; }
        else if (sel==1){ s4=(const float4*)k; hi=(uint2*)g_kh; lo=(uint2*)g_kl; }
        else { s4=(const float4*)v; hi=(uint2*)g_vh; lo=(uint2*)g_vl; }
        float4 f0 = s4[j], f1 = s4[j+1];
        uint2 hv, lv;
        split4(f0, hv, lv); hi[j]=hv;   lo[j]=lv;
        split4(f1, hv, lv); hi[j+1]=hv; lo[j+1]=lv;
    } else if (bid < 8192){
        int i = (bid-6144)*256 + threadIdx.x;
        if (i >= 4*NW8) return;
        int sel = i / NW8, j = (i - sel*NW8)*2;
        const float4* s4; uint2 *hi, *lo;
        if (sel==0){ s4=(const float4*)Wq; hi=(uint2*)g_Wqh; lo=(uint2*)g_Wql; }
        else if (sel==1){ s4=(const float4*)Wk; hi=(uint2*)g_Wkh; lo=(uint2*)g_Wkl; }
        else if (sel==2){ s4=(const float4*)Wv; hi=(uint2*)g_Wvh; lo=(uint2*)g_Wvl; }
        else { s4=(const float4*)Wo; hi=(uint2*)g_Woh; lo=(uint2*)g_Wol; }
        float4 f0 = s4[j], f1 = s4[j+1];
        uint2 hv, lv;
        split4(f0, hv, lv); hi[j]=hv;   lo[j]=lv;
        split4(f1, hv, lv); hi[j+1]=hv; lo[j+1]=lv;
    } else if (bid < 18432){
        int idx = (bid-8192)*256 + threadIdx.x;
        const int tot0 = 3*COUT*DD;
        const int tot1 = 5*COUT*DD;
        if (idx < tot0){
            int t = idx/(COUT*DD); int r = idx%(COUT*DD);
            int co = r/DD, ci = r%DD;
            float vv = w0[(co*DD+ci)*3 + t];
            bf16 h = __float2bfloat16(vv);
            g_wt0h[idx] = h;
            g_wt0l[idx] = __float2bfloat16(vv - __bfloat162float(h));
        }
        if (idx < tot1){
            int t = idx/(COUT*DD); int r = idx%(COUT*DD);
            int co = r/DD, ci = r%DD;
            float vv = w1[(co*DD+ci)*5 + t];
            bf16 h = __float2bfloat16(vv);
            g_wt1h[idx] = h;
            g_wt1l[idx] = __float2bfloat16(vv - __bfloat162float(h));
        }
    } else {
        int i = (bid-18432)*256 + threadIdx.x;
        unsigned int b = __ballot_sync(0xffffffffu, mask[i] != 0);
        if ((threadIdx.x & 31) == 0) g_mbits[i >> 5] = b;
    }
}

// km = g_km + g_kc, split to head-layout hi/lo (2 float4/thread)
__global__ void cvt_km(int n8){
    int i0 = (blockIdx.x*blockDim.x + threadIdx.x);
    if (i0 >= n8) return;
    int j = i0*2;
    #pragma unroll
    for (int t=0;t<2;t++){
        float4 a = ((const float4*)g_km)[j+t];
        float4 b = ((const float4*)g_kc)[j+t];
        a.x += b.x; a.y += b.y; a.z += b.z; a.w += b.w;
        uint2 hv, lv; split4(a, hv, lv);
        ((uint2*)g_kmh)[j+t]=hv; ((uint2*)g_kml)[j+t]=lv;
    }
}

// ---------------- fused tensor-core bf16x3 GEMM (R9 proven: 8 warps, 32x64) -----
#define BKS 16
#define SST 24           // smem row stride in bf16 elems (16 data + 8 pad)
#define TILEE 3072       // one 128-row array: 128*SST elems
#define STGE 12288       // 4 arrays per stage (elems)
#define NSTG 3
#define SMEM_BYTES 73728 // 3 stages * 24576B

__device__ __forceinline__ void cp_stage_rt(int mode, bf16* smem, int slot, int k0,
                                            int m0, int n0, int tid){
    const bf16 *Ah, *Al, *Bh, *Bl;
    if (mode==0){ Ah=g_qh; Al=g_ql; Bh=g_Wqh; Bl=g_Wql; }
    else if (mode==1){ Ah=g_kh; Al=g_kl; Bh=g_Wkh; Bl=g_Wkl; }
    else if (mode==3){ Ah=g_vh; Al=g_vl; Bh=g_Wvh; Bl=g_Wvl; }
    else if (mode==4){ Ah=g_kh; Al=g_kl; Bh=g_wt0h; Bl=g_wt0l; }
    else { Ah=g_kh; Al=g_kl; Bh=g_wt1h; Bl=g_wt1l; }

    const int row = tid >> 1;
    const int cg  = (tid & 1)*8;
    bf16* pA = smem + slot*STGE + row*SST + cg;

    if (mode<=3){
        size_t off = (size_t)(m0+row)*DD + k0 + cg;
        __pipeline_memcpy_async(pA,         Ah+off, 16);
        __pipeline_memcpy_async(pA+TILEE,   Al+off, 16);
        size_t offb = (size_t)(n0+row)*DD + k0 + cg;
        __pipeline_memcpy_async(pA+2*TILEE, Bh+offb, 16);
        __pipeline_memcpy_async(pA+3*TILEE, Bl+offb, 16);
    } else {
        const int pad = (mode==4)?1:2;
        int t   = k0 >> 10;
        int ci0 = k0 & 1023;
        int m   = m0 + row;
        int bidx = m >> 11;
        int s2  = (m & 2047) + t - pad;
        bool ok = (s2 >= 0 && s2 < SS);
        size_t off = ok ? ((size_t)(bidx*SS + s2)*DD + ci0 + cg) : 0;
        size_t zf  = ok ? 0 : 16;
        __pipeline_memcpy_async(pA,         Ah+off, 16, zf);
        __pipeline_memcpy_async(pA+TILEE,   Al+off, 16, zf);
        size_t offb = ((size_t)t*COUT + (n0+row))*DD + ci0 + cg;
        __pipeline_memcpy_async(pA+2*TILEE, Bh+offb, 16);
        __pipeline_memcpy_async(pA+3*TILEE, Bl+offb, 16);
    }
}

__global__ __launch_bounds__(256,2) void mma_gemm_fused(
        const float* __restrict__ gate, const float* __restrict__ cb0,
        const float* __restrict__ cb1){
    extern __shared__ __align__(16) bf16 smem[];
    const int tid  = threadIdx.x;
    const int wid  = tid >> 5, lane = tid & 31;
    const int wm   = wid >> 1, wn = wid & 1;     // warp grid 4x2, warp tile 32x64

    int bid = blockIdx.x;
    int mode, r;
    if (bid < 128)      { mode=5; r=bid; }
    else if (bid < 256) { mode=4; r=bid-128; }
    else if (bid < 512) { mode=1; r=bid-256; }
    else if (bid < 768) { mode=0; r=bid-512; }
    else                { mode=3; r=bid-768; }
    int m0, n0;
    if (mode>=4){ n0=(r&3)*128; m0=(r>>2)*128; }
    else        { n0=(r&7)*128; m0=(r>>3)*128; }
    const int STEPS = (mode==5) ? 320 : (mode==4) ? 192 : 64;

    wmma::fragment<wmma::accumulator,16,16,16,float> facc[2][4];
    #pragma unroll
    for (int i=0;i<2;i++)
        #pragma unroll
        for (int j=0;j<4;j++) wmma::fill_fragment(facc[i][j], 0.0f);

    cp_stage_rt(mode, smem, 0, 0,   m0, n0, tid); __pipeline_commit();
    cp_stage_rt(mode, smem, 1, BKS, m0, n0, tid); __pipeline_commit();

    for (int s=0; s<STEPS; s++){
        __pipeline_wait_prior(1);
        __syncthreads();

        const bf16* sAh = smem + (s%NSTG)*STGE;
        const bf16* sAl = sAh + TILEE;
        const bf16* sBh = sAh + 2*TILEE;
        const bf16* sBl = sAh + 3*TILEE;

        wmma::fragment<wmma::matrix_a,16,16,16,bf16,wmma::row_major> fah[2], fal[2];
        #pragma unroll
        for (int i=0;i<2;i++){
            wmma::load_matrix_sync(fah[i], sAh + (wm*32 + i*16)*SST, SST);
            wmma::load_matrix_sync(fal[i], sAl + (wm*32 + i*16)*SST, SST);
        }
        #pragma unroll
        for (int j=0;j<4;j++){
            wmma::fragment<wmma::matrix_b,16,16,16,bf16,wmma::col_major> fbh, fbl;
            wmma::load_matrix_sync(fbh, sBh + (wn*64 + j*16)*SST, SST);
            wmma::load_matrix_sync(fbl, sBl + (wn*64 + j*16)*SST, SST);
            #pragma unroll
            for (int i=0;i<2;i++){
                wmma::mma_sync(facc[i][j], fah[i], fbh, facc[i][j]);
                wmma::mma_sync(facc[i][j], fah[i], fbl, facc[i][j]);
                wmma::mma_sync(facc[i][j], fal[i], fbh, facc[i][j]);
            }
        }
        if (s+2 < STEPS) cp_stage_rt(mode, smem, (s+2)%NSTG, (s+2)*BKS, m0, n0, tid);
        __pipeline_commit();
    }
    __syncthreads();

    // ---- epilogue: per-warp 1KB scratch chunks ----
    float* scr = (float*)smem + wid*256;   // 16x16 per warp
    #pragma unroll
    for (int i=0;i<2;i++){
        #pragma unroll
        for (int j=0;j<4;j++){
            wmma::store_matrix_sync(scr, facc[i][j], 16, wmma::mem_row_major);
            __syncwarp();
            #pragma unroll
            for (int t=0;t<8;t++){
                int e = lane + t*32;
                int row = e >> 4, col = e & 15;
                float val = scr[e];
                int gm = m0 + wm*32 + i*16 + row;
                int gn = n0 + wn*64 + j*16 + col;
                int bidx = gm>>11, ss2 = gm&2047;
                if (mode==0 || mode==3){
                    int hh2 = gn>>6, d = gn&63;
                    size_t idx = (((size_t)bidx*HH+hh2)*SS+ss2)*DHD + d;
                    bf16 hv = __float2bfloat16(val);
                    bf16 lv = __float2bfloat16(val - __bfloat162float(hv));
                    if (mode==0){ g_qhh[idx]=hv; g_qhl[idx]=lv; }
                    else        { g_vhh[idx]=hv; g_vhl[idx]=lv; }
                } else if (mode==1){
                    int hh2 = gn>>6, d = gn&63;
                    float sc = 1.0f - sigm(gate[hh2]);
                    g_km[(((size_t)bidx*HH+hh2)*SS+ss2)*DHD + d] = val*sc;
                } else {
                    const int branch = (mode==5) ? 1 : 0;
                    const float* bias = branch ? cb1 : cb0;
                    int gc = branch*COUT + gn;
                    int hh2 = gc>>6, d = gc&63;
                    float g = sigm(gate[hh2]);
                    g_kc[(((size_t)bidx*HH+hh2)*SS+ss2)*DHD + d] = g*(val + bias[gn]);
                }
            }
            __syncwarp();
        }
    }
}

// ---------------- out-projection GEMM (R9 proven shape) -------------------------
__device__ __forceinline__ void cp_out(bf16* smem, int slot, int k0,
                                       int m0, int n0, int tid){
    const int row = tid >> 1;
    const int cg  = (tid & 1)*8;
    bf16* pA = smem + slot*STGE + row*SST + cg;
    size_t off  = (size_t)(m0+row)*DD + k0 + cg;
    size_t offb = (size_t)(n0+row)*DD + k0 + cg;
    __pipeline_memcpy_async(pA,         g_aoh+off, 16);
    __pipeline_memcpy_async(pA+TILEE,   g_aol+off, 16);
    __pipeline_memcpy_async(pA+2*TILEE, g_Woh+offb, 16);
    __pipeline_memcpy_async(pA+3*TILEE, g_Wol+offb, 16);
}

__global__ __launch_bounds__(256,2) void mma_gemm_out(
        float* __restrict__ dstp, const float* __restrict__ bo){
    extern __shared__ __align__(16) bf16 smem[];
    const int tid  = threadIdx.x;
    const int wid  = tid >> 5, lane = tid & 31;
    const int wm   = wid >> 1, wn = wid & 1;
    const int m0   = blockIdx.y*128;
    const int n0   = blockIdx.x*128;
    const int STEPS = DD/BKS;

    wmma::fragment<wmma::accumulator,16,16,16,float> facc[2][4];
    #pragma unroll
    for (int i=0;i<2;i++)
        #pragma unroll
        for (int j=0;j<4;j++) wmma::fill_fragment(facc[i][j], 0.0f);

    cp_out(smem, 0, 0,   m0, n0, tid); __pipeline_commit();
    cp_out(smem, 1, BKS, m0, n0, tid); __pipeline_commit();

    for (int s=0; s<STEPS; s++){
        __pipeline_wait_prior(1);
        __syncthreads();

        const bf16* sAh = smem + (s%NSTG)*STGE;
        const bf16* sAl = sAh + TILEE;
        const bf16* sBh = sAh + 2*TILEE;
        const bf16* sBl = sAh + 3*TILEE;

        wmma::fragment<wmma::matrix_a,16,16,16,bf16,wmma::row_major> fah[2], fal[2];
        #pragma unroll
        for (int i=0;i<2;i++){
            wmma::load_matrix_sync(fah[i], sAh + (wm*32 + i*16)*SST, SST);
            wmma::load_matrix_sync(fal[i], sAl + (wm*32 + i*16)*SST, SST);
        }
        #pragma unroll
        for (int j=0;j<4;j++){
            wmma::fragment<wmma::matrix_b,16,16,16,bf16,wmma::col_major> fbh, fbl;
            wmma::load_matrix_sync(fbh, sBh + (wn*64 + j*16)*SST, SST);
            wmma::load_matrix_sync(fbl, sBl + (wn*64 + j*16)*SST, SST);
            #pragma unroll
            for (int i=0;i<2;i++){
                wmma::mma_sync(facc[i][j], fah[i], fbh, facc[i][j]);
                wmma::mma_sync(facc[i][j], fah[i], fbl, facc[i][j]);
                wmma::mma_sync(facc[i][j], fal[i], fbh, facc[i][j]);
            }
        }
        if (s+2 < STEPS) cp_out(smem, (s+2)%NSTG, (s+2)*BKS, m0, n0, tid);
        __pipeline_commit();
    }
    __syncthreads();

    float* scr = (float*)smem + wid*256;
    #pragma unroll
    for (int i=0;i<2;i++){
        #pragma unroll
        for (int j=0;j<4;j++){
            wmma::store_matrix_sync(scr, facc[i][j], 16, wmma::mem_row_major);
            __syncwarp();
            #pragma unroll
            for (int t=0;t<8;t++){
                int e = lane + t*32;
                int row2 = e >> 4, col = e & 15;
                int gm = m0 + wm*32 + i*16 + row2;
                int gn = n0 + wn*64 + j*16 + col;
                dstp[(size_t)gm*DD + gn] = scr[e] + bo[gn];
            }
            __syncwarp();
        }
    }
}

// ---------------- flash attention: 4 warps/CTA, FQT=64, 2 CTAs/SM ---------------
#define FQT 64
#define FKT 64
#define FST 72       // bf16 row stride (64 data + 8 pad)
#define KVB 9216     // one 64x72 bf16 array in bytes
#define BUFBY 36864  // Kh,Kl,Vh,Vl per stage
#define O_P 73728    // after 2 KV stages; Ph (9216B) + Pl (9216B); also Q staging
#define FSM 92160

__device__ __forceinline__ void cp_kv(unsigned char* fsm, int slot, size_t base,
                                      int k0, int tid){
    #pragma unroll
    for (int i=0;i<16;i++){
        int idx = tid + i*128;
        int arr = idx >> 9, e = idx & 511;
        int row = e >> 3, c = (e & 7)*8;
        const bf16* src = g_kmh;
        if (arr==1) src = g_kml;
        if (arr==2) src = g_vhh;
        if (arr==3) src = g_vhl;
        __pipeline_memcpy_async((bf16*)(fsm + slot*BUFBY + arr*KVB) + row*FST + c,
                                src + base + (size_t)(k0+row)*DHD + c, 16);
    }
}
__device__ __forceinline__ void st_pair(bf16* hp, bf16* lp, int off, float a, float b){
    bf16 ha = __float2bfloat16(a);
    bf16 hb = __float2bfloat16(b);
    __nv_bfloat162 hv; hv.x = ha; hv.y = hb;
    __nv_bfloat162 lv;
    lv.x = __float2bfloat16(a - __bfloat162float(ha));
    lv.y = __float2bfloat16(b - __bfloat162float(hb));
    *(__nv_bfloat162*)(hp + off) = hv;
    *(__nv_bfloat162*)(lp + off) = lv;
}

__global__ __launch_bounds__(128,2) void flash_wmma(int dummy){
    extern __shared__ __align__(16) unsigned char fsm[];
    const int tid = threadIdx.x;
    const int w = tid >> 5, lane = tid & 31;
    const int bh = blockIdx.y;
    const int b = bh >> 4, h = bh & 15;
    const int q0 = blockIdx.x*FQT;
    const size_t base = (size_t)bh*SS*DHD;
    const int NI = SS/FKT;   // 32

    bf16* Ph = (bf16*)(fsm + O_P);
    bf16* Pl = (bf16*)(fsm + O_P + 9216);

    // stage Q tile (64x64 hi/lo) into P region
    #pragma unroll
    for (int i=0;i<4;i++){
        int idx = tid + i*128;
        int row = idx >> 3, c = (idx & 7)*8;
        *(uint4*)(Ph + row*FST + c) = *(const uint4*)(g_qhh + base + (size_t)(q0+row)*DHD + c);
        *(uint4*)(Pl + row*FST + c) = *(const uint4*)(g_qhl + base + (size_t)(q0+row)*DHD + c);
    }
    cp_kv(fsm, 0, base, 0,   tid); __pipeline_commit();
    cp_kv(fsm, 1, base, FKT, tid); __pipeline_commit();
    __syncthreads();

    wmma::fragment<wmma::matrix_a,16,16,16,bf16,wmma::row_major> qah[4], qal[4];
    #pragma unroll
    for (int kk=0;kk<4;kk++){
        wmma::load_matrix_sync(qah[kk], Ph + (w*16)*FST + kk*16, FST);
        wmma::load_matrix_sync(qal[kk], Pl + (w*16)*FST + kk*16, FST);
    }
    __syncthreads();   // Q fragments in regs before P region is overwritten

    wmma::fragment<wmma::accumulator,16,16,16,float> oacc[4];
    #pragma unroll
    for (int j=0;j<4;j++) wmma::fill_fragment(oacc[j], 0.0f);

    const int r0 = lane >> 2;
    const int grow0 = q0 + w*16 + r0;
    float mr0 = -CUDART_INF_F, mr1 = -CUDART_INF_F;
    float l0 = 0.0f, l1 = 0.0f;
    const float scl = 0.125f;

    for (int kb=0; kb<NI; kb++){
        __pipeline_wait_prior(1);
        __syncthreads();

        const int cur = kb & 1;
        bf16* Kh = (bf16*)(fsm + cur*BUFBY);
        bf16* Kl = (bf16*)(fsm + cur*BUFBY + KVB);
        bf16* Vh = (bf16*)(fsm + cur*BUFBY + 2*KVB);
        bf16* Vl = (bf16*)(fsm + cur*BUFBY + 3*KVB);

        wmma::fragment<wmma::accumulator,16,16,16,float> sacc[4];
        #pragma unroll
        for (int j=0;j<4;j++) wmma::fill_fragment(sacc[j], 0.0f);

        #pragma unroll
        for (int kk=0;kk<4;kk++){
            #pragma unroll
            for (int j=0;j<4;j++){
                wmma::fragment<wmma::matrix_b,16,16,16,bf16,wmma::col_major> kbh, kbl;
                wmma::load_matrix_sync(kbh, Kh + (j*16)*FST + kk*16, FST);
                wmma::load_matrix_sync(kbl, Kl + (j*16)*FST + kk*16, FST);
                wmma::mma_sync(sacc[j], qah[kk], kbh, sacc[j]);
                wmma::mma_sync(sacc[j], qah[kk], kbl, sacc[j]);
                wmma::mma_sync(sacc[j], qal[kk], kbh, sacc[j]);
            }
        }

        uint2 w0u = *(const uint2*)(g_mbits + ((size_t)b*SS + grow0)*(SS/32) + kb*2);
        uint2 w1u = *(const uint2*)(g_mbits + ((size_t)b*SS + grow0 + 8)*(SS/32) + kb*2);
        unsigned long long mb0 = ((unsigned long long)w0u.y << 32) | w0u.x;
        unsigned long long mb1 = ((unsigned long long)w1u.y << 32) | w1u.x;

        float rm0 = -CUDART_INF_F, rm1 = -CUDART_INF_F;
        #pragma unroll
        for (int j=0;j<4;j++){
            float* x = sacc[j].x;
            int c0 = j*16 + (lane&3)*2;
            x[0] = ((mb0 >> c0)     & 1) ? x[0]*scl : -1e9f;
            x[1] = ((mb0 >> (c0+1)) & 1) ? x[1]*scl : -1e9f;
            x[4] = ((mb0 >> (c0+8)) & 1) ? x[4]*scl : -1e9f;
            x[5] = ((mb0 >> (c0+9)) & 1) ? x[5]*scl : -1e9f;
            x[2] = ((mb1 >> c0)     & 1) ? x[2]*scl : -1e9f;
            x[3] = ((mb1 >> (c0+1)) & 1) ? x[3]*scl : -1e9f;
            x[6] = ((mb1 >> (c0+8)) & 1) ? x[6]*scl : -1e9f;
            x[7] = ((mb1 >> (c0+9)) & 1) ? x[7]*scl : -1e9f;
            rm0 = fmaxf(rm0, fmaxf(fmaxf(x[0],x[1]), fmaxf(x[4],x[5])));
            rm1 = fmaxf(rm1, fmaxf(fmaxf(x[2],x[3]), fmaxf(x[6],x[7])));
        }
        rm0 = fmaxf(rm0, __shfl_xor_sync(0xffffffffu, rm0, 1));
        rm0 = fmaxf(rm0, __shfl_xor_sync(0xffffffffu, rm0, 2));
        rm1 = fmaxf(rm1, __shfl_xor_sync(0xffffffffu, rm1, 1));
        rm1 = fmaxf(rm1, __shfl_xor_sync(0xffffffffu, rm1, 2));

        float mn0 = fmaxf(mr0, rm0), mn1 = fmaxf(mr1, rm1);
        float cr0 = __expf(mr0 - mn0), cr1 = __expf(mr1 - mn1);

        float ps0 = 0.0f, ps1 = 0.0f;
        const int lr0 = w*16 + r0;
        #pragma unroll
        for (int j=0;j<4;j++){
            float* x = sacc[j].x;
            int c0 = j*16 + (lane&3)*2;
            float p00 = __expf(x[0]-mn0), p01 = __expf(x[1]-mn0);
            float p08 = __expf(x[4]-mn0), p09 = __expf(x[5]-mn0);
            float p10 = __expf(x[2]-mn1), p11 = __expf(x[3]-mn1);
            float p18 = __expf(x[6]-mn1), p19 = __expf(x[7]-mn1);
            ps0 += (p00+p01) + (p08+p09);
            ps1 += (p10+p11) + (p18+p19);
            st_pair(Ph, Pl, lr0*FST + c0,       p00, p01);
            st_pair(Ph, Pl, lr0*FST + c0 + 8,   p08, p09);
            st_pair(Ph, Pl, (lr0+8)*FST + c0,   p10, p11);
            st_pair(Ph, Pl, (lr0+8)*FST + c0+8, p18, p19);
        }
        ps0 += __shfl_xor_sync(0xffffffffu, ps0, 1);
        ps0 += __shfl_xor_sync(0xffffffffu, ps0, 2);
        ps1 += __shfl_xor_sync(0xffffffffu, ps1, 1);
        ps1 += __shfl_xor_sync(0xffffffffu, ps1, 2);

        l0 = l0*cr0 + ps0;  l1 = l1*cr1 + ps1;
        mr0 = mn0;          mr1 = mn1;

        #pragma unroll
        for (int j=0;j<4;j++){
            float* x = oacc[j].x;
            x[0]*=cr0; x[1]*=cr0; x[4]*=cr0; x[5]*=cr0;
            x[2]*=cr1; x[3]*=cr1; x[6]*=cr1; x[7]*=cr1;
        }
        __syncwarp();

        #pragma unroll
        for (int kk=0;kk<4;kk++){
            wmma::fragment<wmma::matrix_a,16,16,16,bf16,wmma::row_major> pah, pal;
            wmma::load_matrix_sync(pah, Ph + (w*16)*FST + kk*16, FST);
            wmma::load_matrix_sync(pal, Pl + (w*16)*FST + kk*16, FST);
            #pragma unroll
            for (int j=0;j<4;j++){
                wmma::fragment<wmma::matrix_b,16,16,16,bf16,wmma::row_major> vbh, vbl;
                wmma::load_matrix_sync(vbh, Vh + (kk*16)*FST + j*16, FST);
                wmma::load_matrix_sync(vbl, Vl + (kk*16)*FST + j*16, FST);
                wmma::mma_sync(oacc[j], pah, vbh, oacc[j]);
                wmma::mma_sync(oacc[j], pah, vbl, oacc[j]);
                wmma::mma_sync(oacc[j], pal, vbh, oacc[j]);
            }
        }

        // all warps must finish reading slot `cur` before it is refilled
        // (2-stage ring: (kb+2)&1 == cur). This barrier was missing in R11.
        __syncthreads();
        if (kb+2 < NI) cp_kv(fsm, cur, base, (kb+2)*FKT, tid);
        __pipeline_commit();
    }

    float inv0 = 1.0f / l0, inv1 = 1.0f / l1;
    int gr0 = q0 + w*16 + r0, gr1 = gr0 + 8;
    size_t ro0 = ((size_t)b*SS + gr0)*DD + h*DHD;
    size_t ro1 = ((size_t)b*SS + gr1)*DD + h*DHD;
    #pragma unroll
    for (int j=0;j<4;j++){
        float* x = oacc[j].x;
        int c0 = j*16 + (lane&3)*2;
        st_pair(g_aoh + ro0, g_aol + ro0, c0,     x[0]*inv0, x[1]*inv0);
        st_pair(g_aoh + ro0, g_aol + ro0, c0 + 8, x[4]*inv0, x[5]*inv0);
        st_pair(g_aoh + ro1, g_aol + ro1, c0,     x[2]*inv1, x[3]*inv1);
        st_pair(g_aoh + ro1, g_aol + ro1, c0 + 8, x[6]*inv1, x[7]*inv1);
    }
}

// ---------------- launch ------------------------------------------------------
extern "C" void kernel_launch(void* const* d_in, const int* in_sizes, int n_in,
                              void* d_out, int out_size){
    const float* q    = (const float*)d_in[0];
    const float* k    = (const float*)d_in[1];
    const float* v    = (const float*)d_in[2];
    const int*   mask = (const int*)  d_in[3];
    const float* Wq   = (const float*)d_in[4];
    const float* Wk   = (const float*)d_in[5];
    const float* Wv   = (const float*)d_in[6];
    const float* Wo   = (const float*)d_in[7];
    const float* bo   = (const float*)d_in[8];
    const float* cw0  = (const float*)d_in[9];
    const float* cb0  = (const float*)d_in[10];
    const float* cw1  = (const float*)d_in[11];
    const float* cb1  = (const float*)d_in[12];
    const float* gate = (const float*)d_in[13];
    float* out = (float*)d_out;

    prep_all<<<51200,256>>>(q, k, v, Wq, Wk, Wv, Wo, cw0, cw1, mask);

    cudaFuncSetAttribute(mma_gemm_fused, cudaFuncAttributeMaxDynamicSharedMemorySize, SMEM_BYTES);
    cudaFuncSetAttribute(mma_gemm_out,   cudaFuncAttributeMaxDynamicSharedMemorySize, SMEM_BYTES);
    cudaFuncSetAttribute(flash_wmma,     cudaFuncAttributeMaxDynamicSharedMemorySize, FSM);

    mma_gemm_fused<<<1024,256,SMEM_BYTES>>>(gate, cb0, cb1);

    cvt_km<<<(NBIG8+255)/256,256>>>(NBIG8);   // (g_km + g_kc) -> kmh/kml

    flash_wmma<<<dim3(SS/FQT, BB*HH), 128, FSM>>>(0);

    mma_gemm_out<<<dim3(DD/128, MTOT/128),256,SMEM_BYTES>>>(out, bo);
}

// round 15
// speedup vs baseline: 1.2670x; 1.0088x over previous
#include <cuda_runtime.h>
#include <cuda_bf16.h>
#include <mma.h>
#include <cuda_pipeline.h>
#include <math_constants.h>

using namespace nvcuda;

#define BB 2
#define SS 2048
#define DD 1024
#define HH 16
#define DHD 64
#define MTOT (BB*SS)   // 4096
#define COUT 512

typedef __nv_bfloat16 bf16;

// ---------------- scratch (device globals; no allocation allowed) -------------
__device__ float g_km[BB*HH*SS*DHD];   // (1-g)*kh   (head layout)
__device__ float g_kc[BB*HH*SS*DHD];   // g*(conv+bias) (head layout)

// bf16 hi/lo splits (GEMM inputs)
__device__ bf16 g_qh[MTOT*DD],  g_ql[MTOT*DD];
__device__ bf16 g_kh[MTOT*DD],  g_kl[MTOT*DD];
__device__ bf16 g_vh[MTOT*DD],  g_vl[MTOT*DD];
__device__ bf16 g_aoh[MTOT*DD], g_aol[MTOT*DD];
__device__ bf16 g_Wqh[DD*DD], g_Wql[DD*DD];
__device__ bf16 g_Wkh[DD*DD], g_Wkl[DD*DD];
__device__ bf16 g_Wvh[DD*DD], g_Wvl[DD*DD];
__device__ bf16 g_Woh[DD*DD], g_Wol[DD*DD];
__device__ bf16 g_wt0h[3*COUT*DD], g_wt0l[3*COUT*DD];   // [t][co][ci]
__device__ bf16 g_wt1h[5*COUT*DD], g_wt1l[5*COUT*DD];

// bf16 hi/lo, head layout [B,H,S,DH] (attention inputs)
__device__ bf16 g_qhh[BB*HH*SS*DHD], g_qhl[BB*HH*SS*DHD];   // Q PRE-SCALED by 0.125
__device__ bf16 g_kmh[BB*HH*SS*DHD], g_kml[BB*HH*SS*DHD];
__device__ bf16 g_vhh[BB*HH*SS*DHD], g_vhl[BB*HH*SS*DHD];

// packed mask bits: [B][S][S/32] words
__device__ unsigned int g_mbits[BB*SS*(SS/32)];

__device__ __forceinline__ float sigm(float x){ return 1.0f/(1.0f+__expf(-x)); }

__device__ __forceinline__ void split4(float4 f, uint2& hv, uint2& lv){
    float fv[4] = {f.x, f.y, f.z, f.w};
    unsigned int hw[4], lw[4];
    #pragma unroll
    for (int j=0;j<4;j++){
        bf16 h = __float2bfloat16(fv[j]);
        bf16 l = __float2bfloat16(fv[j] - __bfloat162float(h));
        hw[j] = (unsigned int)__bfloat16_as_ushort(h);
        lw[j] = (unsigned int)__bfloat16_as_ushort(l);
    }
    hv = make_uint2(hw[0] | (hw[1]<<16), hw[2] | (hw[3]<<16));
    lv = make_uint2(lw[0] | (lw[1]<<16), lw[2] | (lw[3]<<16));
}

// ---------------- ONE fused prep kernel ----------------------------------------
#define NBIG4 (MTOT*DD/4)
#define NBIG8 (NBIG4/2)
#define NW8   (DD*DD/8)

__global__ void prep_all(const float* __restrict__ q, const float* __restrict__ k,
                         const float* __restrict__ v,
                         const float* __restrict__ Wq, const float* __restrict__ Wk,
                         const float* __restrict__ Wv, const float* __restrict__ Wo,
                         const float* __restrict__ w0, const float* __restrict__ w1,
                         const int* __restrict__ mask){
    int bid = blockIdx.x;
    if (bid < 6144){
        int i = bid*256 + threadIdx.x;
        if (i >= 3*NBIG8) return;
        int sel = i / NBIG8, j = (i - sel*NBIG8)*2;
        const float4* s4; uint2 *hi, *lo;
        if (sel==0){ s4=(const float4*)q; hi=(uint2*)g_qh; lo=(uint2*)g_ql; }
        else if (sel==1){ s4=(const float4*)k; hi=(uint2*)g_kh; lo=(uint2*)g_kl; }
        else { s4=(const float4*)v; hi=(uint2*)g_vh; lo=(uint2*)g_vl; }
        float4 f0 = s4[j], f1 = s4[j+1];
        uint2 hv, lv;
        split4(f0, hv, lv); hi[j]=hv;   lo[j]=lv;
        split4(f1, hv, lv); hi[j+1]=hv; lo[j+1]=lv;
    } else if (bid < 8192){
        int i = (bid-6144)*256 + threadIdx.x;
        if (i >= 4*NW8) return;
        int sel = i / NW8, j = (i - sel*NW8)*2;
        const float4* s4; uint2 *hi, *lo;
        if (sel==0){ s4=(const float4*)Wq; hi=(uint2*)g_Wqh; lo=(uint2*)g_Wql; }
        else if (sel==1){ s4=(const float4*)Wk; hi=(uint2*)g_Wkh; lo=(uint2*)g_Wkl; }
        else if (sel==2){ s4=(const float4*)Wv; hi=(uint2*)g_Wvh; lo=(uint2*)g_Wvl; }
        else { s4=(const float4*)Wo; hi=(uint2*)g_Woh; lo=(uint2*)g_Wol; }
        float4 f0 = s4[j], f1 = s4[j+1];
        uint2 hv, lv;
        split4(f0, hv, lv); hi[j]=hv;   lo[j]=lv;
        split4(f1, hv, lv); hi[j+1]=hv; lo[j+1]=lv;
    } else if (bid < 18432){
        int idx = (bid-8192)*256 + threadIdx.x;
        const int tot0 = 3*COUT*DD;
        const int tot1 = 5*COUT*DD;
        if (idx < tot0){
            int t = idx/(COUT*DD); int r = idx%(COUT*DD);
            int co = r/DD, ci = r%DD;
            float vv = w0[(co*DD+ci)*3 + t];
            bf16 h = __float2bfloat16(vv);
            g_wt0h[idx] = h;
            g_wt0l[idx] = __float2bfloat16(vv - __bfloat162float(h));
        }
        if (idx < tot1){
            int t = idx/(COUT*DD); int r = idx%(COUT*DD);
            int co = r/DD, ci = r%DD;
            float vv = w1[(co*DD+ci)*5 + t];
            bf16 h = __float2bfloat16(vv);
            g_wt1h[idx] = h;
            g_wt1l[idx] = __float2bfloat16(vv - __bfloat162float(h));
        }
    } else {
        int i = (bid-18432)*256 + threadIdx.x;
        unsigned int b = __ballot_sync(0xffffffffu, mask[i] != 0);
        if ((threadIdx.x & 31) == 0) g_mbits[i >> 5] = b;
    }
}

// km = g_km + g_kc, split to head-layout hi/lo (2 float4/thread)
__global__ void cvt_km(int n8){
    int i0 = (blockIdx.x*blockDim.x + threadIdx.x);
    if (i0 >= n8) return;
    int j = i0*2;
    #pragma unroll
    for (int t=0;t<2;t++){
        float4 a = ((const float4*)g_km)[j+t];
        float4 b = ((const float4*)g_kc)[j+t];
        a.x += b.x; a.y += b.y; a.z += b.z; a.w += b.w;
        uint2 hv, lv; split4(a, hv, lv);
        ((uint2*)g_kmh)[j+t]=hv; ((uint2*)g_kml)[j+t]=lv;
    }
}

// ---------------- fused tensor-core bf16x3 GEMM (R9 proven: 8 warps, 32x64) -----
#define BKS 16
#define SST 24           // smem row stride in bf16 elems (16 data + 8 pad)
#define TILEE 3072       // one 128-row array: 128*SST elems
#define STGE 12288       // 4 arrays per stage (elems)
#define NSTG 3
#define SMEM_BYTES 73728 // 3 stages * 24576B

__device__ __forceinline__ void cp_stage_rt(int mode, bf16* smem, int slot, int k0,
                                            int m0, int n0, int tid){
    const bf16 *Ah, *Al, *Bh, *Bl;
    if (mode==0){ Ah=g_qh; Al=g_ql; Bh=g_Wqh; Bl=g_Wql; }
    else if (mode==1){ Ah=g_kh; Al=g_kl; Bh=g_Wkh; Bl=g_Wkl; }
    else if (mode==3){ Ah=g_vh; Al=g_vl; Bh=g_Wvh; Bl=g_Wvl; }
    else if (mode==4){ Ah=g_kh; Al=g_kl; Bh=g_wt0h; Bl=g_wt0l; }
    else { Ah=g_kh; Al=g_kl; Bh=g_wt1h; Bl=g_wt1l; }

    const int row = tid >> 1;
    const int cg  = (tid & 1)*8;
    bf16* pA = smem + slot*STGE + row*SST + cg;

    if (mode<=3){
        size_t off = (size_t)(m0+row)*DD + k0 + cg;
        __pipeline_memcpy_async(pA,         Ah+off, 16);
        __pipeline_memcpy_async(pA+TILEE,   Al+off, 16);
        size_t offb = (size_t)(n0+row)*DD + k0 + cg;
        __pipeline_memcpy_async(pA+2*TILEE, Bh+offb, 16);
        __pipeline_memcpy_async(pA+3*TILEE, Bl+offb, 16);
    } else {
        const int pad = (mode==4)?1:2;
        int t   = k0 >> 10;
        int ci0 = k0 & 1023;
        int m   = m0 + row;
        int bidx = m >> 11;
        int s2  = (m & 2047) + t - pad;
        bool ok = (s2 >= 0 && s2 < SS);
        size_t off = ok ? ((size_t)(bidx*SS + s2)*DD + ci0 + cg) : 0;
        size_t zf  = ok ? 0 : 16;
        __pipeline_memcpy_async(pA,         Ah+off, 16, zf);
        __pipeline_memcpy_async(pA+TILEE,   Al+off, 16, zf);
        size_t offb = ((size_t)t*COUT + (n0+row))*DD + ci0 + cg;
        __pipeline_memcpy_async(pA+2*TILEE, Bh+offb, 16);
        __pipeline_memcpy_async(pA+3*TILEE, Bl+offb, 16);
    }
}

__global__ __launch_bounds__(256,2) void mma_gemm_fused(
        const float* __restrict__ gate, const float* __restrict__ cb0,
        const float* __restrict__ cb1){
    extern __shared__ __align__(16) bf16 smem[];
    const int tid  = threadIdx.x;
    const int wid  = tid >> 5, lane = tid & 31;
    const int wm   = wid >> 1, wn = wid & 1;     // warp grid 4x2, warp tile 32x64

    int bid = blockIdx.x;
    int mode, r;
    if (bid < 128)      { mode=5; r=bid; }
    else if (bid < 256) { mode=4; r=bid-128; }
    else if (bid < 512) { mode=1; r=bid-256; }
    else if (bid < 768) { mode=0; r=bid-512; }
    else                { mode=3; r=bid-768; }
    int m0, n0;
    if (mode>=4){ n0=(r&3)*128; m0=(r>>2)*128; }
    else        { n0=(r&7)*128; m0=(r>>3)*128; }
    const int STEPS = (mode==5) ? 320 : (mode==4) ? 192 : 64;

    wmma::fragment<wmma::accumulator,16,16,16,float> facc[2][4];
    #pragma unroll
    for (int i=0;i<2;i++)
        #pragma unroll
        for (int j=0;j<4;j++) wmma::fill_fragment(facc[i][j], 0.0f);

    cp_stage_rt(mode, smem, 0, 0,   m0, n0, tid); __pipeline_commit();
    cp_stage_rt(mode, smem, 1, BKS, m0, n0, tid); __pipeline_commit();

    for (int s=0; s<STEPS; s++){
        __pipeline_wait_prior(1);
        __syncthreads();

        const bf16* sAh = smem + (s%NSTG)*STGE;
        const bf16* sAl = sAh + TILEE;
        const bf16* sBh = sAh + 2*TILEE;
        const bf16* sBl = sAh + 3*TILEE;

        wmma::fragment<wmma::matrix_a,16,16,16,bf16,wmma::row_major> fah[2], fal[2];
        #pragma unroll
        for (int i=0;i<2;i++){
            wmma::load_matrix_sync(fah[i], sAh + (wm*32 + i*16)*SST, SST);
            wmma::load_matrix_sync(fal[i], sAl + (wm*32 + i*16)*SST, SST);
        }
        #pragma unroll
        for (int j=0;j<4;j++){
            wmma::fragment<wmma::matrix_b,16,16,16,bf16,wmma::col_major> fbh, fbl;
            wmma::load_matrix_sync(fbh, sBh + (wn*64 + j*16)*SST, SST);
            wmma::load_matrix_sync(fbl, sBl + (wn*64 + j*16)*SST, SST);
            #pragma unroll
            for (int i=0;i<2;i++){
                wmma::mma_sync(facc[i][j], fah[i], fbh, facc[i][j]);
                wmma::mma_sync(facc[i][j], fah[i], fbl, facc[i][j]);
                wmma::mma_sync(facc[i][j], fal[i], fbh, facc[i][j]);
            }
        }
        if (s+2 < STEPS) cp_stage_rt(mode, smem, (s+2)%NSTG, (s+2)*BKS, m0, n0, tid);
        __pipeline_commit();
    }
    __syncthreads();

    // ---- epilogue: per-warp 1KB scratch chunks ----
    float* scr = (float*)smem + wid*256;   // 16x16 per warp
    #pragma unroll
    for (int i=0;i<2;i++){
        #pragma unroll
        for (int j=0;j<4;j++){
            wmma::store_matrix_sync(scr, facc[i][j], 16, wmma::mem_row_major);
            __syncwarp();
            #pragma unroll
            for (int t=0;t<8;t++){
                int e = lane + t*32;
                int row = e >> 4, col = e & 15;
                float val = scr[e];
                int gm = m0 + wm*32 + i*16 + row;
                int gn = n0 + wn*64 + j*16 + col;
                int bidx = gm>>11, ss2 = gm&2047;
                if (mode==0 || mode==3){
                    int hh2 = gn>>6, d = gn&63;
                    size_t idx = (((size_t)bidx*HH+hh2)*SS+ss2)*DHD + d;
                    if (mode==0) val *= 0.125f;   // fold attention scale into Q (exact)
                    bf16 hv = __float2bfloat16(val);
                    bf16 lv = __float2bfloat16(val - __bfloat162float(hv));
                    if (mode==0){ g_qhh[idx]=hv; g_qhl[idx]=lv; }
                    else        { g_vhh[idx]=hv; g_vhl[idx]=lv; }
                } else if (mode==1){
                    int hh2 = gn>>6, d = gn&63;
                    float sc = 1.0f - sigm(gate[hh2]);
                    g_km[(((size_t)bidx*HH+hh2)*SS+ss2)*DHD + d] = val*sc;
                } else {
                    const int branch = (mode==5) ? 1 : 0;
                    const float* bias = branch ? cb1 : cb0;
                    int gc = branch*COUT + gn;
                    int hh2 = gc>>6, d = gc&63;
                    float g = sigm(gate[hh2]);
                    g_kc[(((size_t)bidx*HH+hh2)*SS+ss2)*DHD + d] = g*(val + bias[gn]);
                }
            }
            __syncwarp();
        }
    }
}

// ---------------- out-projection GEMM (R9 proven shape) -------------------------
__device__ __forceinline__ void cp_out(bf16* smem, int slot, int k0,
                                       int m0, int n0, int tid){
    const int row = tid >> 1;
    const int cg  = (tid & 1)*8;
    bf16* pA = smem + slot*STGE + row*SST + cg;
    size_t off  = (size_t)(m0+row)*DD + k0 + cg;
    size_t offb = (size_t)(n0+row)*DD + k0 + cg;
    __pipeline_memcpy_async(pA,         g_aoh+off, 16);
    __pipeline_memcpy_async(pA+TILEE,   g_aol+off, 16);
    __pipeline_memcpy_async(pA+2*TILEE, g_Woh+offb, 16);
    __pipeline_memcpy_async(pA+3*TILEE, g_Wol+offb, 16);
}

__global__ __launch_bounds__(256,2) void mma_gemm_out(
        float* __restrict__ dstp, const float* __restrict__ bo){
    extern __shared__ __align__(16) bf16 smem[];
    const int tid  = threadIdx.x;
    const int wid  = tid >> 5, lane = tid & 31;
    const int wm   = wid >> 1, wn = wid & 1;
    const int m0   = blockIdx.y*128;
    const int n0   = blockIdx.x*128;
    const int STEPS = DD/BKS;

    wmma::fragment<wmma::accumulator,16,16,16,float> facc[2][4];
    #pragma unroll
    for (int i=0;i<2;i++)
        #pragma unroll
        for (int j=0;j<4;j++) wmma::fill_fragment(facc[i][j], 0.0f);

    cp_out(smem, 0, 0,   m0, n0, tid); __pipeline_commit();
    cp_out(smem, 1, BKS, m0, n0, tid); __pipeline_commit();

    for (int s=0; s<STEPS; s++){
        __pipeline_wait_prior(1);
        __syncthreads();

        const bf16* sAh = smem + (s%NSTG)*STGE;
        const bf16* sAl = sAh + TILEE;
        const bf16* sBh = sAh + 2*TILEE;
        const bf16* sBl = sAh + 3*TILEE;

        wmma::fragment<wmma::matrix_a,16,16,16,bf16,wmma::row_major> fah[2], fal[2];
        #pragma unroll
        for (int i=0;i<2;i++){
            wmma::load_matrix_sync(fah[i], sAh + (wm*32 + i*16)*SST, SST);
            wmma::load_matrix_sync(fal[i], sAl + (wm*32 + i*16)*SST, SST);
        }
        #pragma unroll
        for (int j=0;j<4;j++){
            wmma::fragment<wmma::matrix_b,16,16,16,bf16,wmma::col_major> fbh, fbl;
            wmma::load_matrix_sync(fbh, sBh + (wn*64 + j*16)*SST, SST);
            wmma::load_matrix_sync(fbl, sBl + (wn*64 + j*16)*SST, SST);
            #pragma unroll
            for (int i=0;i<2;i++){
                wmma::mma_sync(facc[i][j], fah[i], fbh, facc[i][j]);
                wmma::mma_sync(facc[i][j], fah[i], fbl, facc[i][j]);
                wmma::mma_sync(facc[i][j], fal[i], fbh, facc[i][j]);
            }
        }
        if (s+2 < STEPS) cp_out(smem, (s+2)%NSTG, (s+2)*BKS, m0, n0, tid);
        __pipeline_commit();
    }
    __syncthreads();

    float* scr = (float*)smem + wid*256;
    #pragma unroll
    for (int i=0;i<2;i++){
        #pragma unroll
        for (int j=0;j<4;j++){
            wmma::store_matrix_sync(scr, facc[i][j], 16, wmma::mem_row_major);
            __syncwarp();
            #pragma unroll
            for (int t=0;t<8;t++){
                int e = lane + t*32;
                int row2 = e >> 4, col = e & 15;
                int gm = m0 + wm*32 + i*16 + row2;
                int gn = n0 + wn*64 + j*16 + col;
                dstp[(size_t)gm*DD + gn] = scr[e] + bo[gn];
            }
            __syncwarp();
        }
    }
}

// ---------------- flash attention: 4 warps/CTA, FQT=64, 2 CTAs/SM ---------------
// Q pre-scaled by 0.125; P stored hi/lo (precision-critical, see R13 notes)
#define FQT 64
#define FKT 64
#define FST 72       // bf16 row stride (64 data + 8 pad)
#define KVB 9216     // one 64x72 bf16 array in bytes
#define BUFBY 36864  // Kh,Kl,Vh,Vl per stage
#define O_P 73728    // after 2 KV stages; Ph (9216B) + Pl (9216B); also Q staging
#define FSM 92160

__device__ __forceinline__ void cp_kv(unsigned char* fsm, int slot, size_t base,
                                      int k0, int tid){
    #pragma unroll
    for (int i=0;i<16;i++){
        int idx = tid + i*128;
        int arr = idx >> 9, e = idx & 511;
        int row = e >> 3, c = (e & 7)*8;
        const bf16* src = g_kmh;
        if (arr==1) src = g_kml;
        if (arr==2) src = g_vhh;
        if (arr==3) src = g_vhl;
        __pipeline_memcpy_async((bf16*)(fsm + slot*BUFBY + arr*KVB) + row*FST + c,
                                src + base + (size_t)(k0+row)*DHD + c, 16);
    }
}
__device__ __forceinline__ void st_pair(bf16* hp, bf16* lp, int off, float a, float b){
    bf16 ha = __float2bfloat16(a);
    bf16 hb = __float2bfloat16(b);
    __nv_bfloat162 hv; hv.x = ha; hv.y = hb;
    __nv_bfloat162 lv;
    lv.x = __float2bfloat16(a - __bfloat162float(ha));
    lv.y = __float2bfloat16(b - __bfloat162float(hb));
    *(__nv_bfloat162*)(hp + off) = hv;
    *(__nv_bfloat162*)(lp + off) = lv;
}

__global__ __launch_bounds__(128,2) void flash_wmma(int dummy){
    extern __shared__ __align__(16) unsigned char fsm[];
    const int tid = threadIdx.x;
    const int w = tid >> 5, lane = tid & 31;
    const int bh = blockIdx.y;
    const int b = bh >> 4, h = bh & 15;
    const int q0 = blockIdx.x*FQT;
    const size_t base = (size_t)bh*SS*DHD;
    const int NI = SS/FKT;   // 32

    bf16* Ph = (bf16*)(fsm + O_P);
    bf16* Pl = (bf16*)(fsm + O_P + 9216);

    // stage Q tile (64x64 hi/lo) into P region
    #pragma unroll
    for (int i=0;i<4;i++){
        int idx = tid + i*128;
        int row = idx >> 3, c = (idx & 7)*8;
        *(uint4*)(Ph + row*FST + c) = *(const uint4*)(g_qhh + base + (size_t)(q0+row)*DHD + c);
        *(uint4*)(Pl + row*FST + c) = *(const uint4*)(g_qhl + base + (size_t)(q0+row)*DHD + c);
    }
    cp_kv(fsm, 0, base, 0,   tid); __pipeline_commit();
    cp_kv(fsm, 1, base, FKT, tid); __pipeline_commit();
    __syncthreads();

    wmma::fragment<wmma::matrix_a,16,16,16,bf16,wmma::row_major> qah[4], qal[4];
    #pragma unroll
    for (int kk=0;kk<4;kk++){
        wmma::load_matrix_sync(qah[kk], Ph + (w*16)*FST + kk*16, FST);
        wmma::load_matrix_sync(qal[kk], Pl + (w*16)*FST + kk*16, FST);
    }
    __syncthreads();   // Q fragments in regs before P region is overwritten

    wmma::fragment<wmma::accumulator,16,16,16,float> oacc[4];
    #pragma unroll
    for (int j=0;j<4;j++) wmma::fill_fragment(oacc[j], 0.0f);

    const int r0 = lane >> 2;
    const int grow0 = q0 + w*16 + r0;
    float mr0 = -CUDART_INF_F, mr1 = -CUDART_INF_F;
    float l0 = 0.0f, l1 = 0.0f;

    for (int kb=0; kb<NI; kb++){
        __pipeline_wait_prior(1);
        __syncthreads();

        const int cur = kb & 1;
        bf16* Kh = (bf16*)(fsm + cur*BUFBY);
        bf16* Kl = (bf16*)(fsm + cur*BUFBY + KVB);
        bf16* Vh = (bf16*)(fsm + cur*BUFBY + 2*KVB);
        bf16* Vl = (bf16*)(fsm + cur*BUFBY + 3*KVB);

        wmma::fragment<wmma::accumulator,16,16,16,float> sacc[4];
        #pragma unroll
        for (int j=0;j<4;j++) wmma::fill_fragment(sacc[j], 0.0f);

        #pragma unroll
        for (int kk=0;kk<4;kk++){
            #pragma unroll
            for (int j=0;j<4;j++){
                wmma::fragment<wmma::matrix_b,16,16,16,bf16,wmma::col_major> kbh, kbl;
                wmma::load_matrix_sync(kbh, Kh + (j*16)*FST + kk*16, FST);
                wmma::load_matrix_sync(kbl, Kl + (j*16)*FST + kk*16, FST);
                wmma::mma_sync(sacc[j], qah[kk], kbh, sacc[j]);
                wmma::mma_sync(sacc[j], qah[kk], kbl, sacc[j]);
                wmma::mma_sync(sacc[j], qal[kk], kbh, sacc[j]);
            }
        }

        // scores arrive pre-scaled (Q folded). Mask: fast path when fully set.
        uint2 w0u = *(const uint2*)(g_mbits + ((size_t)b*SS + grow0)*(SS/32) + kb*2);
        uint2 w1u = *(const uint2*)(g_mbits + ((size_t)b*SS + grow0 + 8)*(SS/32) + kb*2);
        if ((w0u.x & w0u.y & w1u.x & w1u.y) != 0xFFFFFFFFu){
            unsigned long long mb0 = ((unsigned long long)w0u.y << 32) | w0u.x;
            unsigned long long mb1 = ((unsigned long long)w1u.y << 32) | w1u.x;
            #pragma unroll
            for (int j=0;j<4;j++){
                float* x = sacc[j].x;
                int c0 = j*16 + (lane&3)*2;
                if (!((mb0 >> c0)     & 1)) x[0] = -1e9f;
                if (!((mb0 >> (c0+1)) & 1)) x[1] = -1e9f;
                if (!((mb0 >> (c0+8)) & 1)) x[4] = -1e9f;
                if (!((mb0 >> (c0+9)) & 1)) x[5] = -1e9f;
                if (!((mb1 >> c0)     & 1)) x[2] = -1e9f;
                if (!((mb1 >> (c0+1)) & 1)) x[3] = -1e9f;
                if (!((mb1 >> (c0+8)) & 1)) x[6] = -1e9f;
                if (!((mb1 >> (c0+9)) & 1)) x[7] = -1e9f;
            }
        }

        float rm0 = -CUDART_INF_F, rm1 = -CUDART_INF_F;
        #pragma unroll
        for (int j=0;j<4;j++){
            float* x = sacc[j].x;
            rm0 = fmaxf(rm0, fmaxf(fmaxf(x[0],x[1]), fmaxf(x[4],x[5])));
            rm1 = fmaxf(rm1, fmaxf(fmaxf(x[2],x[3]), fmaxf(x[6],x[7])));
        }
        rm0 = fmaxf(rm0, __shfl_xor_sync(0xffffffffu, rm0, 1));
        rm0 = fmaxf(rm0, __shfl_xor_sync(0xffffffffu, rm0, 2));
        rm1 = fmaxf(rm1, __shfl_xor_sync(0xffffffffu, rm1, 1));
        rm1 = fmaxf(rm1, __shfl_xor_sync(0xffffffffu, rm1, 2));

        float mn0 = fmaxf(mr0, rm0), mn1 = fmaxf(mr1, rm1);
        float cr0 = __expf(mr0 - mn0), cr1 = __expf(mr1 - mn1);

        float ps0 = 0.0f, ps1 = 0.0f;
        const int lr0 = w*16 + r0;
        #pragma unroll
        for (int j=0;j<4;j++){
            float* x = sacc[j].x;
            int c0 = j*16 + (lane&3)*2;
            float p00 = __expf(x[0]-mn0), p01 = __expf(x[1]-mn0);
            float p08 = __expf(x[4]-mn0), p09 = __expf(x[5]-mn0);
            float p10 = __expf(x[2]-mn1), p11 = __expf(x[3]-mn1);
            float p18 = __expf(x[6]-mn1), p19 = __expf(x[7]-mn1);
            ps0 += (p00+p01) + (p08+p09);
            ps1 += (p10+p11) + (p18+p19);
            st_pair(Ph, Pl, lr0*FST + c0,       p00, p01);
            st_pair(Ph, Pl, lr0*FST + c0 + 8,   p08, p09);
            st_pair(Ph, Pl, (lr0+8)*FST + c0,   p10, p11);
            st_pair(Ph, Pl, (lr0+8)*FST + c0+8, p18, p19);
        }
        ps0 += __shfl_xor_sync(0xffffffffu, ps0, 1);
        ps0 += __shfl_xor_sync(0xffffffffu, ps0, 2);
        ps1 += __shfl_xor_sync(0xffffffffu, ps1, 1);
        ps1 += __shfl_xor_sync(0xffffffffu, ps1, 2);

        l0 = l0*cr0 + ps0;  l1 = l1*cr1 + ps1;
        mr0 = mn0;          mr1 = mn1;

        #pragma unroll
        for (int j=0;j<4;j++){
            float* x = oacc[j].x;
            x[0]*=cr0; x[1]*=cr0; x[4]*=cr0; x[5]*=cr0;
            x[2]*=cr1; x[3]*=cr1; x[6]*=cr1; x[7]*=cr1;
        }
        __syncwarp();

        #pragma unroll
        for (int kk=0;kk<4;kk++){
            wmma::fragment<wmma::matrix_a,16,16,16,bf16,wmma::row_major> pah, pal;
            wmma::load_matrix_sync(pah, Ph + (w*16)*FST + kk*16, FST);
            wmma::load_matrix_sync(pal, Pl + (w*16)*FST + kk*16, FST);
            #pragma unroll
            for (int j=0;j<4;j++){
                wmma::fragment<wmma::matrix_b,16,16,16,bf16,wmma::row_major> vbh, vbl;
                wmma::load_matrix_sync(vbh, Vh + (kk*16)*FST + j*16, FST);
                wmma::load_matrix_sync(vbl, Vl + (kk*16)*FST + j*16, FST);
                wmma::mma_sync(oacc[j], pah, vbh, oacc[j]);
                wmma::mma_sync(oacc[j], pah, vbl, oacc[j]);
                wmma::mma_sync(oacc[j], pal, vbh, oacc[j]);
            }
        }

        // all warps must finish reading slot `cur` before it is refilled
        __syncthreads();
        if (kb+2 < NI) cp_kv(fsm, cur, base, (kb+2)*FKT, tid);
        __pipeline_commit();
    }

    float inv0 = 1.0f / l0, inv1 = 1.0f / l1;
    int gr0 = q0 + w*16 + r0, gr1 = gr0 + 8;
    size_t ro0 = ((size_t)b*SS + gr0)*DD + h*DHD;
    size_t ro1 = ((size_t)b*SS + gr1)*DD + h*DHD;
    #pragma unroll
    for (int j=0;j<4;j++){
        float* x = oacc[j].x;
        int c0 = j*16 + (lane&3)*2;
        st_pair(g_aoh + ro0, g_aol + ro0, c0,     x[0]*inv0, x[1]*inv0);
        st_pair(g_aoh + ro0, g_aol + ro0, c0 + 8, x[4]*inv0, x[5]*inv0);
        st_pair(g_aoh + ro1, g_aol + ro1, c0,     x[2]*inv1, x[3]*inv1);
        st_pair(g_aoh + ro1, g_aol + ro1, c0 + 8, x[6]*inv1, x[7]*inv1);
    }
}

// ---------------- launch ------------------------------------------------------
extern "C" void kernel_launch(void* const* d_in, const int* in_sizes, int n_in,
                              void* d_out, int out_size){
    const float* q    = (const float*)d_in[0];
    const float* k    = (const float*)d_in[1];
    const float* v    = (const float*)d_in[2];
    const int*   mask = (const int*)  d_in[3];
    const float* Wq   = (const float*)d_in[4];
    const float* Wk   = (const float*)d_in[5];
    const float* Wv   = (const float*)d_in[6];
    const float* Wo   = (const float*)d_in[7];
    const float* bo   = (const float*)d_in[8];
    const float* cw0  = (const float*)d_in[9];
    const float* cb0  = (const float*)d_in[10];
    const float* cw1  = (const float*)d_in[11];
    const float* cb1  = (const float*)d_in[12];
    const float* gate = (const float*)d_in[13];
    float* out = (float*)d_out;

    prep_all<<<51200,256>>>(q, k, v, Wq, Wk, Wv, Wo, cw0, cw1, mask);

    cudaFuncSetAttribute(mma_gemm_fused, cudaFuncAttributeMaxDynamicSharedMemorySize, SMEM_BYTES);
    cudaFuncSetAttribute(mma_gemm_out,   cudaFuncAttributeMaxDynamicSharedMemorySize, SMEM_BYTES);
    cudaFuncSetAttribute(flash_wmma,     cudaFuncAttributeMaxDynamicSharedMemorySize, FSM);

    mma_gemm_fused<<<1024,256,SMEM_BYTES>>>(gate, cb0, cb1);

    cvt_km<<<(NBIG8+255)/256,256>>>(NBIG8);   // (g_km + g_kc) -> kmh/kml

    flash_wmma<<<dim3(SS/FQT, BB*HH), 128, FSM>>>(0);

    mma_gemm_out<<<dim3(DD/128, MTOT/128),256,SMEM_BYTES>>>(out, bo);
}

// round 16
// speedup vs baseline: 1.2847x; 1.0140x over previous
#include <cuda_runtime.h>
#include <cuda_bf16.h>
#include <mma.h>
#include <cuda_pipeline.h>
#include <math_constants.h>

using namespace nvcuda;

#define BB 2
#define SS 2048
#define DD 1024
#define HH 16
#define DHD 64
#define MTOT (BB*SS)   // 4096
#define COUT 512

typedef __nv_bfloat16 bf16;

// ---------------- scratch (device globals; no allocation allowed) -------------
__device__ float g_km[BB*HH*SS*DHD];   // (1-g)*kh   (head layout)
__device__ float g_kc[BB*HH*SS*DHD];   // g*(conv+bias) (head layout)

// bf16 hi/lo splits (GEMM inputs)
__device__ bf16 g_qh[MTOT*DD],  g_ql[MTOT*DD];
__device__ bf16 g_kh[MTOT*DD],  g_kl[MTOT*DD];
__device__ bf16 g_vh[MTOT*DD],  g_vl[MTOT*DD];
__device__ bf16 g_aoh[MTOT*DD], g_aol[MTOT*DD];
__device__ bf16 g_Wqh[DD*DD], g_Wql[DD*DD];
__device__ bf16 g_Wkh[DD*DD], g_Wkl[DD*DD];
__device__ bf16 g_Wvh[DD*DD], g_Wvl[DD*DD];
__device__ bf16 g_Woh[DD*DD], g_Wol[DD*DD];
__device__ bf16 g_wt0h[3*COUT*DD], g_wt0l[3*COUT*DD];   // [t][co][ci]
__device__ bf16 g_wt1h[5*COUT*DD], g_wt1l[5*COUT*DD];

// bf16 hi/lo, head layout [B,H,S,DH] (attention inputs)
__device__ bf16 g_qhh[BB*HH*SS*DHD], g_qhl[BB*HH*SS*DHD];   // Q PRE-SCALED by 0.125
__device__ bf16 g_kmh[BB*HH*SS*DHD], g_kml[BB*HH*SS*DHD];
__device__ bf16 g_vhh[BB*HH*SS*DHD], g_vhl[BB*HH*SS*DHD];

// packed mask bits: [B][S][S/32] words
__device__ unsigned int g_mbits[BB*SS*(SS/32)];

__device__ __forceinline__ float sigm(float x){ return 1.0f/(1.0f+__expf(-x)); }

__device__ __forceinline__ void split4(float4 f, uint2& hv, uint2& lv){
    float fv[4] = {f.x, f.y, f.z, f.w};
    unsigned int hw[4], lw[4];
    #pragma unroll
    for (int j=0;j<4;j++){
        bf16 h = __float2bfloat16(fv[j]);
        bf16 l = __float2bfloat16(fv[j] - __bfloat162float(h));
        hw[j] = (unsigned int)__bfloat16_as_ushort(h);
        lw[j] = (unsigned int)__bfloat16_as_ushort(l);
    }
    hv = make_uint2(hw[0] | (hw[1]<<16), hw[2] | (hw[3]<<16));
    lv = make_uint2(lw[0] | (lw[1]<<16), lw[2] | (lw[3]<<16));
}

// ---------------- ONE fused prep kernel ----------------------------------------
#define NBIG4 (MTOT*DD/4)
#define NBIG8 (NBIG4/2)
#define NW8   (DD*DD/8)

__global__ void prep_all(const float* __restrict__ q, const float* __restrict__ k,
                         const float* __restrict__ v,
                         const float* __restrict__ Wq, const float* __restrict__ Wk,
                         const float* __restrict__ Wv, const float* __restrict__ Wo,
                         const float* __restrict__ w0, const float* __restrict__ w1,
                         const int* __restrict__ mask){
    int bid = blockIdx.x;
    if (bid < 6144){
        int i = bid*256 + threadIdx.x;
        if (i >= 3*NBIG8) return;
        int sel = i / NBIG8, j = (i - sel*NBIG8)*2;
        const float4* s4; uint2 *hi, *lo;
        if (sel==0){ s4=(const float4*)q; hi=(uint2*)g_qh; lo=(uint2*)g_ql; }
        else if (sel==1){ s4=(const float4*)k; hi=(uint2*)g_kh; lo=(uint2*)g_kl; }
        else { s4=(const float4*)v; hi=(uint2*)g_vh; lo=(uint2*)g_vl; }
        float4 f0 = s4[j], f1 = s4[j+1];
        uint2 hv, lv;
        split4(f0, hv, lv); hi[j]=hv;   lo[j]=lv;
        split4(f1, hv, lv); hi[j+1]=hv; lo[j+1]=lv;
    } else if (bid < 8192){
        int i = (bid-6144)*256 + threadIdx.x;
        if (i >= 4*NW8) return;
        int sel = i / NW8, j = (i - sel*NW8)*2;
        const float4* s4; uint2 *hi, *lo;
        if (sel==0){ s4=(const float4*)Wq; hi=(uint2*)g_Wqh; lo=(uint2*)g_Wql; }
        else if (sel==1){ s4=(const float4*)Wk; hi=(uint2*)g_Wkh; lo=(uint2*)g_Wkl; }
        else if (sel==2){ s4=(const float4*)Wv; hi=(uint2*)g_Wvh; lo=(uint2*)g_Wvl; }
        else { s4=(const float4*)Wo; hi=(uint2*)g_Woh; lo=(uint2*)g_Wol; }
        float4 f0 = s4[j], f1 = s4[j+1];
        uint2 hv, lv;
        split4(f0, hv, lv); hi[j]=hv;   lo[j]=lv;
        split4(f1, hv, lv); hi[j+1]=hv; lo[j+1]=lv;
    } else if (bid < 18432){
        int idx = (bid-8192)*256 + threadIdx.x;
        const int tot0 = 3*COUT*DD;
        const int tot1 = 5*COUT*DD;
        if (idx < tot0){
            int t = idx/(COUT*DD); int r = idx%(COUT*DD);
            int co = r/DD, ci = r%DD;
            float vv = w0[(co*DD+ci)*3 + t];
            bf16 h = __float2bfloat16(vv);
            g_wt0h[idx] = h;
            g_wt0l[idx] = __float2bfloat16(vv - __bfloat162float(h));
        }
        if (idx < tot1){
            int t = idx/(COUT*DD); int r = idx%(COUT*DD);
            int co = r/DD, ci = r%DD;
            float vv = w1[(co*DD+ci)*5 + t];
            bf16 h = __float2bfloat16(vv);
            g_wt1h[idx] = h;
            g_wt1l[idx] = __float2bfloat16(vv - __bfloat162float(h));
        }
    } else {
        int i = (bid-18432)*256 + threadIdx.x;
        unsigned int b = __ballot_sync(0xffffffffu, mask[i] != 0);
        if ((threadIdx.x & 31) == 0) g_mbits[i >> 5] = b;
    }
}

// km = g_km + g_kc, split to head-layout hi/lo (2 float4/thread)
__global__ void cvt_km(int n8){
    int i0 = (blockIdx.x*blockDim.x + threadIdx.x);
    if (i0 >= n8) return;
    int j = i0*2;
    #pragma unroll
    for (int t=0;t<2;t++){
        float4 a = ((const float4*)g_km)[j+t];
        float4 b = ((const float4*)g_kc)[j+t];
        a.x += b.x; a.y += b.y; a.z += b.z; a.w += b.w;
        uint2 hv, lv; split4(a, hv, lv);
        ((uint2*)g_kmh)[j+t]=hv; ((uint2*)g_kml)[j+t]=lv;
    }
}

// ---------------- fused tensor-core bf16x3 GEMM (R9 proven: 8 warps, 32x64) -----
#define BKS 16
#define SST 24           // smem row stride in bf16 elems (16 data + 8 pad)
#define TILEE 3072       // one 128-row array: 128*SST elems
#define STGE 12288       // 4 arrays per stage (elems)
#define NSTG 3
#define SMEM_BYTES 73728 // 3 stages * 24576B

__device__ __forceinline__ void cp_stage_rt(int mode, bf16* smem, int slot, int k0,
                                            int m0, int n0, int tid){
    const bf16 *Ah, *Al, *Bh, *Bl;
    if (mode==0){ Ah=g_qh; Al=g_ql; Bh=g_Wqh; Bl=g_Wql; }
    else if (mode==1){ Ah=g_kh; Al=g_kl; Bh=g_Wkh; Bl=g_Wkl; }
    else if (mode==3){ Ah=g_vh; Al=g_vl; Bh=g_Wvh; Bl=g_Wvl; }
    else if (mode==4){ Ah=g_kh; Al=g_kl; Bh=g_wt0h; Bl=g_wt0l; }
    else { Ah=g_kh; Al=g_kl; Bh=g_wt1h; Bl=g_wt1l; }

    const int row = tid >> 1;
    const int cg  = (tid & 1)*8;
    bf16* pA = smem + slot*STGE + row*SST + cg;

    if (mode<=3){
        size_t off = (size_t)(m0+row)*DD + k0 + cg;
        __pipeline_memcpy_async(pA,         Ah+off, 16);
        __pipeline_memcpy_async(pA+TILEE,   Al+off, 16);
        size_t offb = (size_t)(n0+row)*DD + k0 + cg;
        __pipeline_memcpy_async(pA+2*TILEE, Bh+offb, 16);
        __pipeline_memcpy_async(pA+3*TILEE, Bl+offb, 16);
    } else {
        const int pad = (mode==4)?1:2;
        int t   = k0 >> 10;
        int ci0 = k0 & 1023;
        int m   = m0 + row;
        int bidx = m >> 11;
        int s2  = (m & 2047) + t - pad;
        bool ok = (s2 >= 0 && s2 < SS);
        size_t off = ok ? ((size_t)(bidx*SS + s2)*DD + ci0 + cg) : 0;
        size_t zf  = ok ? 0 : 16;
        __pipeline_memcpy_async(pA,         Ah+off, 16, zf);
        __pipeline_memcpy_async(pA+TILEE,   Al+off, 16, zf);
        size_t offb = ((size_t)t*COUT + (n0+row))*DD + ci0 + cg;
        __pipeline_memcpy_async(pA+2*TILEE, Bh+offb, 16);
        __pipeline_memcpy_async(pA+3*TILEE, Bl+offb, 16);
    }
}

__global__ __launch_bounds__(256,2) void mma_gemm_fused(
        const float* __restrict__ gate, const float* __restrict__ cb0,
        const float* __restrict__ cb1){
    extern __shared__ __align__(16) bf16 smem[];
    const int tid  = threadIdx.x;
    const int wid  = tid >> 5, lane = tid & 31;
    const int wm   = wid >> 1, wn = wid & 1;     // warp grid 4x2, warp tile 32x64

    int bid = blockIdx.x;
    int mode, r;
    if (bid < 128)      { mode=5; r=bid; }
    else if (bid < 256) { mode=4; r=bid-128; }
    else if (bid < 512) { mode=1; r=bid-256; }
    else if (bid < 768) { mode=0; r=bid-512; }
    else                { mode=3; r=bid-768; }
    int m0, n0;
    if (mode>=4){ n0=(r&3)*128; m0=(r>>2)*128; }
    else        { n0=(r&7)*128; m0=(r>>3)*128; }
    const int STEPS = (mode==5) ? 320 : (mode==4) ? 192 : 64;

    wmma::fragment<wmma::accumulator,16,16,16,float> facc[2][4];
    #pragma unroll
    for (int i=0;i<2;i++)
        #pragma unroll
        for (int j=0;j<4;j++) wmma::fill_fragment(facc[i][j], 0.0f);

    cp_stage_rt(mode, smem, 0, 0,   m0, n0, tid); __pipeline_commit();
    cp_stage_rt(mode, smem, 1, BKS, m0, n0, tid); __pipeline_commit();

    for (int s=0; s<STEPS; s++){
        __pipeline_wait_prior(1);
        __syncthreads();

        const bf16* sAh = smem + (s%NSTG)*STGE;
        const bf16* sAl = sAh + TILEE;
        const bf16* sBh = sAh + 2*TILEE;
        const bf16* sBl = sAh + 3*TILEE;

        wmma::fragment<wmma::matrix_a,16,16,16,bf16,wmma::row_major> fah[2], fal[2];
        #pragma unroll
        for (int i=0;i<2;i++){
            wmma::load_matrix_sync(fah[i], sAh + (wm*32 + i*16)*SST, SST);
            wmma::load_matrix_sync(fal[i], sAl + (wm*32 + i*16)*SST, SST);
        }
        #pragma unroll
        for (int j=0;j<4;j++){
            wmma::fragment<wmma::matrix_b,16,16,16,bf16,wmma::col_major> fbh, fbl;
            wmma::load_matrix_sync(fbh, sBh + (wn*64 + j*16)*SST, SST);
            wmma::load_matrix_sync(fbl, sBl + (wn*64 + j*16)*SST, SST);
            #pragma unroll
            for (int i=0;i<2;i++){
                wmma::mma_sync(facc[i][j], fah[i], fbh, facc[i][j]);
                wmma::mma_sync(facc[i][j], fah[i], fbl, facc[i][j]);
                wmma::mma_sync(facc[i][j], fal[i], fbh, facc[i][j]);
            }
        }
        if (s+2 < STEPS) cp_stage_rt(mode, smem, (s+2)%NSTG, (s+2)*BKS, m0, n0, tid);
        __pipeline_commit();
    }
    __syncthreads();

    // ---- epilogue: per-warp 1KB scratch chunks ----
    float* scr = (float*)smem + wid*256;   // 16x16 per warp
    #pragma unroll
    for (int i=0;i<2;i++){
        #pragma unroll
        for (int j=0;j<4;j++){
            wmma::store_matrix_sync(scr, facc[i][j], 16, wmma::mem_row_major);
            __syncwarp();
            #pragma unroll
            for (int t=0;t<8;t++){
                int e = lane + t*32;
                int row = e >> 4, col = e & 15;
                float val = scr[e];
                int gm = m0 + wm*32 + i*16 + row;
                int gn = n0 + wn*64 + j*16 + col;
                int bidx = gm>>11, ss2 = gm&2047;
                if (mode==0 || mode==3){
                    int hh2 = gn>>6, d = gn&63;
                    size_t idx = (((size_t)bidx*HH+hh2)*SS+ss2)*DHD + d;
                    if (mode==0) val *= 0.125f;   // fold attention scale into Q (exact)
                    bf16 hv = __float2bfloat16(val);
                    bf16 lv = __float2bfloat16(val - __bfloat162float(hv));
                    if (mode==0){ g_qhh[idx]=hv; g_qhl[idx]=lv; }
                    else        { g_vhh[idx]=hv; g_vhl[idx]=lv; }
                } else if (mode==1){
                    int hh2 = gn>>6, d = gn&63;
                    float sc = 1.0f - sigm(gate[hh2]);
                    g_km[(((size_t)bidx*HH+hh2)*SS+ss2)*DHD + d] = val*sc;
                } else {
                    const int branch = (mode==5) ? 1 : 0;
                    const float* bias = branch ? cb1 : cb0;
                    int gc = branch*COUT + gn;
                    int hh2 = gc>>6, d = gc&63;
                    float g = sigm(gate[hh2]);
                    g_kc[(((size_t)bidx*HH+hh2)*SS+ss2)*DHD + d] = g*(val + bias[gn]);
                }
            }
            __syncwarp();
        }
    }
}

// ---------------- out-projection GEMM (R9 proven shape) -------------------------
__device__ __forceinline__ void cp_out(bf16* smem, int slot, int k0,
                                       int m0, int n0, int tid){
    const int row = tid >> 1;
    const int cg  = (tid & 1)*8;
    bf16* pA = smem + slot*STGE + row*SST + cg;
    size_t off  = (size_t)(m0+row)*DD + k0 + cg;
    size_t offb = (size_t)(n0+row)*DD + k0 + cg;
    __pipeline_memcpy_async(pA,         g_aoh+off, 16);
    __pipeline_memcpy_async(pA+TILEE,   g_aol+off, 16);
    __pipeline_memcpy_async(pA+2*TILEE, g_Woh+offb, 16);
    __pipeline_memcpy_async(pA+3*TILEE, g_Wol+offb, 16);
}

__global__ __launch_bounds__(256,2) void mma_gemm_out(
        float* __restrict__ dstp, const float* __restrict__ bo){
    extern __shared__ __align__(16) bf16 smem[];
    const int tid  = threadIdx.x;
    const int wid  = tid >> 5, lane = tid & 31;
    const int wm   = wid >> 1, wn = wid & 1;
    const int m0   = blockIdx.y*128;
    const int n0   = blockIdx.x*128;
    const int STEPS = DD/BKS;

    wmma::fragment<wmma::accumulator,16,16,16,float> facc[2][4];
    #pragma unroll
    for (int i=0;i<2;i++)
        #pragma unroll
        for (int j=0;j<4;j++) wmma::fill_fragment(facc[i][j], 0.0f);

    cp_out(smem, 0, 0,   m0, n0, tid); __pipeline_commit();
    cp_out(smem, 1, BKS, m0, n0, tid); __pipeline_commit();

    for (int s=0; s<STEPS; s++){
        __pipeline_wait_prior(1);
        __syncthreads();

        const bf16* sAh = smem + (s%NSTG)*STGE;
        const bf16* sAl = sAh + TILEE;
        const bf16* sBh = sAh + 2*TILEE;
        const bf16* sBl = sAh + 3*TILEE;

        wmma::fragment<wmma::matrix_a,16,16,16,bf16,wmma::row_major> fah[2], fal[2];
        #pragma unroll
        for (int i=0;i<2;i++){
            wmma::load_matrix_sync(fah[i], sAh + (wm*32 + i*16)*SST, SST);
            wmma::load_matrix_sync(fal[i], sAl + (wm*32 + i*16)*SST, SST);
        }
        #pragma unroll
        for (int j=0;j<4;j++){
            wmma::fragment<wmma::matrix_b,16,16,16,bf16,wmma::col_major> fbh, fbl;
            wmma::load_matrix_sync(fbh, sBh + (wn*64 + j*16)*SST, SST);
            wmma::load_matrix_sync(fbl, sBl + (wn*64 + j*16)*SST, SST);
            #pragma unroll
            for (int i=0;i<2;i++){
                wmma::mma_sync(facc[i][j], fah[i], fbh, facc[i][j]);
                wmma::mma_sync(facc[i][j], fah[i], fbl, facc[i][j]);
                wmma::mma_sync(facc[i][j], fal[i], fbh, facc[i][j]);
            }
        }
        if (s+2 < STEPS) cp_out(smem, (s+2)%NSTG, (s+2)*BKS, m0, n0, tid);
        __pipeline_commit();
    }
    __syncthreads();

    float* scr = (float*)smem + wid*256;
    #pragma unroll
    for (int i=0;i<2;i++){
        #pragma unroll
        for (int j=0;j<4;j++){
            wmma::store_matrix_sync(scr, facc[i][j], 16, wmma::mem_row_major);
            __syncwarp();
            #pragma unroll
            for (int t=0;t<8;t++){
                int e = lane + t*32;
                int row2 = e >> 4, col = e & 15;
                int gm = m0 + wm*32 + i*16 + row2;
                int gn = n0 + wn*64 + j*16 + col;
                dstp[(size_t)gm*DD + gn] = scr[e] + bo[gn];
            }
            __syncwarp();
        }
    }
}

// ---------------- flash attention: FKT=32, 4 warps/CTA, 3 CTAs/SM ---------------
// Q pre-scaled by 0.125; P stored hi/lo (precision-critical)
#define FQT 64
#define FKT 32
#define FST 72       // K/V bf16 row stride (64 data + 8 pad)
#define PST 40       // P row stride (32 data + 8 pad)
#define KVB 4608     // one 32x72 bf16 array in bytes
#define BUFBY 18432  // Kh,Kl,Vh,Vl per stage
#define O_P 36864    // after 2 KV stages: Ph (5120B) + Pl (5120B)
#define FSM 47104

__device__ __forceinline__ void cp_kv(unsigned char* fsm, int slot, size_t base,
                                      int k0, int tid){
    #pragma unroll
    for (int i=0;i<8;i++){
        int idx = tid + i*128;
        int arr = idx >> 8, e = idx & 255;
        int row = e >> 3, c = (e & 7)*8;
        const bf16* src = g_kmh;
        if (arr==1) src = g_kml;
        if (arr==2) src = g_vhh;
        if (arr==3) src = g_vhl;
        __pipeline_memcpy_async((bf16*)(fsm + slot*BUFBY + arr*KVB) + row*FST + c,
                                src + base + (size_t)(k0+row)*DHD + c, 16);
    }
}
__device__ __forceinline__ void st_pair(bf16* hp, bf16* lp, int off, float a, float b){
    bf16 ha = __float2bfloat16(a);
    bf16 hb = __float2bfloat16(b);
    __nv_bfloat162 hv; hv.x = ha; hv.y = hb;
    __nv_bfloat162 lv;
    lv.x = __float2bfloat16(a - __bfloat162float(ha));
    lv.y = __float2bfloat16(b - __bfloat162float(hb));
    *(__nv_bfloat162*)(hp + off) = hv;
    *(__nv_bfloat162*)(lp + off) = lv;
}

__global__ __launch_bounds__(128,3) void flash_wmma(int dummy){
    extern __shared__ __align__(16) unsigned char fsm[];
    const int tid = threadIdx.x;
    const int w = tid >> 5, lane = tid & 31;
    const int bh = blockIdx.y;
    const int b = bh >> 4, h = bh & 15;
    const int q0 = blockIdx.x*FQT;
    const size_t base = (size_t)bh*SS*DHD;
    const int NI = SS/FKT;   // 64

    bf16* Ph = (bf16*)(fsm + O_P);
    bf16* Pl = (bf16*)(fsm + O_P + 5120);

    // stage Q tile (64x64 hi/lo) into the KV buffer region (pre-loop only)
    bf16* Qsh = (bf16*)fsm;
    bf16* Qsl = (bf16*)(fsm + 9216);
    #pragma unroll
    for (int i=0;i<4;i++){
        int idx = tid + i*128;
        int row = idx >> 3, c = (idx & 7)*8;
        *(uint4*)(Qsh + row*FST + c) = *(const uint4*)(g_qhh + base + (size_t)(q0+row)*DHD + c);
        *(uint4*)(Qsl + row*FST + c) = *(const uint4*)(g_qhl + base + (size_t)(q0+row)*DHD + c);
    }
    __syncthreads();

    wmma::fragment<wmma::matrix_a,16,16,16,bf16,wmma::row_major> qah[4], qal[4];
    #pragma unroll
    for (int kk=0;kk<4;kk++){
        wmma::load_matrix_sync(qah[kk], Qsh + (w*16)*FST + kk*16, FST);
        wmma::load_matrix_sync(qal[kk], Qsl + (w*16)*FST + kk*16, FST);
    }
    __syncthreads();   // Q in regs before KV buffers are overwritten

    cp_kv(fsm, 0, base, 0,   tid); __pipeline_commit();
    cp_kv(fsm, 1, base, FKT, tid); __pipeline_commit();

    wmma::fragment<wmma::accumulator,16,16,16,float> oacc[4];
    #pragma unroll
    for (int j=0;j<4;j++) wmma::fill_fragment(oacc[j], 0.0f);

    const int r0 = lane >> 2;
    const int grow0 = q0 + w*16 + r0;
    float mr0 = -CUDART_INF_F, mr1 = -CUDART_INF_F;
    float l0 = 0.0f, l1 = 0.0f;

    for (int kb=0; kb<NI; kb++){
        __pipeline_wait_prior(1);
        __syncthreads();

        const int cur = kb & 1;
        bf16* Kh = (bf16*)(fsm + cur*BUFBY);
        bf16* Kl = (bf16*)(fsm + cur*BUFBY + KVB);
        bf16* Vh = (bf16*)(fsm + cur*BUFBY + 2*KVB);
        bf16* Vl = (bf16*)(fsm + cur*BUFBY + 3*KVB);

        wmma::fragment<wmma::accumulator,16,16,16,float> sacc[2];
        #pragma unroll
        for (int j=0;j<2;j++) wmma::fill_fragment(sacc[j], 0.0f);

        #pragma unroll
        for (int kk=0;kk<4;kk++){
            #pragma unroll
            for (int j=0;j<2;j++){
                wmma::fragment<wmma::matrix_b,16,16,16,bf16,wmma::col_major> kbh, kbl;
                wmma::load_matrix_sync(kbh, Kh + (j*16)*FST + kk*16, FST);
                wmma::load_matrix_sync(kbl, Kl + (j*16)*FST + kk*16, FST);
                wmma::mma_sync(sacc[j], qah[kk], kbh, sacc[j]);
                wmma::mma_sync(sacc[j], qah[kk], kbl, sacc[j]);
                wmma::mma_sync(sacc[j], qal[kk], kbh, sacc[j]);
            }
        }

        // scores arrive pre-scaled. Mask: fast path when fully set.
        unsigned int mb0 = g_mbits[((size_t)b*SS + grow0)*(SS/32) + kb];
        unsigned int mb1 = g_mbits[((size_t)b*SS + grow0 + 8)*(SS/32) + kb];
        if ((mb0 & mb1) != 0xFFFFFFFFu){
            #pragma unroll
            for (int j=0;j<2;j++){
                float* x = sacc[j].x;
                int c0 = j*16 + (lane&3)*2;
                if (!((mb0 >> c0)     & 1)) x[0] = -1e9f;
                if (!((mb0 >> (c0+1)) & 1)) x[1] = -1e9f;
                if (!((mb0 >> (c0+8)) & 1)) x[4] = -1e9f;
                if (!((mb0 >> (c0+9)) & 1)) x[5] = -1e9f;
                if (!((mb1 >> c0)     & 1)) x[2] = -1e9f;
                if (!((mb1 >> (c0+1)) & 1)) x[3] = -1e9f;
                if (!((mb1 >> (c0+8)) & 1)) x[6] = -1e9f;
                if (!((mb1 >> (c0+9)) & 1)) x[7] = -1e9f;
            }
        }

        float rm0 = -CUDART_INF_F, rm1 = -CUDART_INF_F;
        #pragma unroll
        for (int j=0;j<2;j++){
            float* x = sacc[j].x;
            rm0 = fmaxf(rm0, fmaxf(fmaxf(x[0],x[1]), fmaxf(x[4],x[5])));
            rm1 = fmaxf(rm1, fmaxf(fmaxf(x[2],x[3]), fmaxf(x[6],x[7])));
        }
        rm0 = fmaxf(rm0, __shfl_xor_sync(0xffffffffu, rm0, 1));
        rm0 = fmaxf(rm0, __shfl_xor_sync(0xffffffffu, rm0, 2));
        rm1 = fmaxf(rm1, __shfl_xor_sync(0xffffffffu, rm1, 1));
        rm1 = fmaxf(rm1, __shfl_xor_sync(0xffffffffu, rm1, 2));

        float mn0 = fmaxf(mr0, rm0), mn1 = fmaxf(mr1, rm1);
        float cr0 = __expf(mr0 - mn0), cr1 = __expf(mr1 - mn1);

        float ps0 = 0.0f, ps1 = 0.0f;
        const int lr0 = w*16 + r0;
        #pragma unroll
        for (int j=0;j<2;j++){
            float* x = sacc[j].x;
            int c0 = j*16 + (lane&3)*2;
            float p00 = __expf(x[0]-mn0), p01 = __expf(x[1]-mn0);
            float p08 = __expf(x[4]-mn0), p09 = __expf(x[5]-mn0);
            float p10 = __expf(x[2]-mn1), p11 = __expf(x[3]-mn1);
            float p18 = __expf(x[6]-mn1), p19 = __expf(x[7]-mn1);
            ps0 += (p00+p01) + (p08+p09);
            ps1 += (p10+p11) + (p18+p19);
            st_pair(Ph, Pl, lr0*PST + c0,       p00, p01);
            st_pair(Ph, Pl, lr0*PST + c0 + 8,   p08, p09);
            st_pair(Ph, Pl, (lr0+8)*PST + c0,   p10, p11);
            st_pair(Ph, Pl, (lr0+8)*PST + c0+8, p18, p19);
        }
        ps0 += __shfl_xor_sync(0xffffffffu, ps0, 1);
        ps0 += __shfl_xor_sync(0xffffffffu, ps0, 2);
        ps1 += __shfl_xor_sync(0xffffffffu, ps1, 1);
        ps1 += __shfl_xor_sync(0xffffffffu, ps1, 2);

        l0 = l0*cr0 + ps0;  l1 = l1*cr1 + ps1;
        mr0 = mn0;          mr1 = mn1;

        #pragma unroll
        for (int j=0;j<4;j++){
            float* x = oacc[j].x;
            x[0]*=cr0; x[1]*=cr0; x[4]*=cr0; x[5]*=cr0;
            x[2]*=cr1; x[3]*=cr1; x[6]*=cr1; x[7]*=cr1;
        }
        __syncwarp();

        #pragma unroll
        for (int kk=0;kk<2;kk++){
            wmma::fragment<wmma::matrix_a,16,16,16,bf16,wmma::row_major> pah, pal;
            wmma::load_matrix_sync(pah, Ph + (w*16)*PST + kk*16, PST);
            wmma::load_matrix_sync(pal, Pl + (w*16)*PST + kk*16, PST);
            #pragma unroll
            for (int j=0;j<4;j++){
                wmma::fragment<wmma::matrix_b,16,16,16,bf16,wmma::row_major> vbh, vbl;
                wmma::load_matrix_sync(vbh, Vh + (kk*16)*FST + j*16, FST);
                wmma::load_matrix_sync(vbl, Vl + (kk*16)*FST + j*16, FST);
                wmma::mma_sync(oacc[j], pah, vbh, oacc[j]);
                wmma::mma_sync(oacc[j], pah, vbl, oacc[j]);
                wmma::mma_sync(oacc[j], pal, vbh, oacc[j]);
            }
        }

        // all warps must finish reading slot `cur` before it is refilled
        __syncthreads();
        if (kb+2 < NI) cp_kv(fsm, cur, base, (kb+2)*FKT, tid);
        __pipeline_commit();
    }

    float inv0 = 1.0f / l0, inv1 = 1.0f / l1;
    int gr0 = q0 + w*16 + r0, gr1 = gr0 + 8;
    size_t ro0 = ((size_t)b*SS + gr0)*DD + h*DHD;
    size_t ro1 = ((size_t)b*SS + gr1)*DD + h*DHD;
    #pragma unroll
    for (int j=0;j<4;j++){
        float* x = oacc[j].x;
        int c0 = j*16 + (lane&3)*2;
        st_pair(g_aoh + ro0, g_aol + ro0, c0,     x[0]*inv0, x[1]*inv0);
        st_pair(g_aoh + ro0, g_aol + ro0, c0 + 8, x[4]*inv0, x[5]*inv0);
        st_pair(g_aoh + ro1, g_aol + ro1, c0,     x[2]*inv1, x[3]*inv1);
        st_pair(g_aoh + ro1, g_aol + ro1, c0 + 8, x[6]*inv1, x[7]*inv1);
    }
}

// ---------------- launch ------------------------------------------------------
extern "C" void kernel_launch(void* const* d_in, const int* in_sizes, int n_in,
                              void* d_out, int out_size){
    const float* q    = (const float*)d_in[0];
    const float* k    = (const float*)d_in[1];
    const float* v    = (const float*)d_in[2];
    const int*   mask = (const int*)  d_in[3];
    const float* Wq   = (const float*)d_in[4];
    const float* Wk   = (const float*)d_in[5];
    const float* Wv   = (const float*)d_in[6];
    const float* Wo   = (const float*)d_in[7];
    const float* bo   = (const float*)d_in[8];
    const float* cw0  = (const float*)d_in[9];
    const float* cb0  = (const float*)d_in[10];
    const float* cw1  = (const float*)d_in[11];
    const float* cb1  = (const float*)d_in[12];
    const float* gate = (const float*)d_in[13];
    float* out = (float*)d_out;

    prep_all<<<51200,256>>>(q, k, v, Wq, Wk, Wv, Wo, cw0, cw1, mask);

    cudaFuncSetAttribute(mma_gemm_fused, cudaFuncAttributeMaxDynamicSharedMemorySize, SMEM_BYTES);
    cudaFuncSetAttribute(mma_gemm_out,   cudaFuncAttributeMaxDynamicSharedMemorySize, SMEM_BYTES);
    cudaFuncSetAttribute(flash_wmma,     cudaFuncAttributeMaxDynamicSharedMemorySize, FSM);

    mma_gemm_fused<<<1024,256,SMEM_BYTES>>>(gate, cb0, cb1);

    cvt_km<<<(NBIG8+255)/256,256>>>(NBIG8);   // (g_km + g_kc) -> kmh/kml

    flash_wmma<<<dim3(SS/FQT, BB*HH), 128, FSM>>>(0);

    mma_gemm_out<<<dim3(DD/128, MTOT/128),256,SMEM_BYTES>>>(out, bo);
}

// round 17
// speedup vs baseline: 1.3013x; 1.0129x over previous
#include <cuda_runtime.h>
#include <cuda_bf16.h>
#include <mma.h>
#include <cuda_pipeline.h>
#include <math_constants.h>

using namespace nvcuda;

#define BB 2
#define SS 2048
#define DD 1024
#define HH 16
#define DHD 64
#define MTOT (BB*SS)   // 4096
#define COUT 512

typedef __nv_bfloat16 bf16;

// ---------------- scratch (device globals; no allocation allowed) -------------
__device__ float g_km[BB*HH*SS*DHD];   // (1-g)*kh   (head layout)
__device__ float g_kc[BB*HH*SS*DHD];   // g*(conv+bias) (head layout)

// bf16 hi/lo splits (GEMM inputs)
__device__ bf16 g_qh[MTOT*DD],  g_ql[MTOT*DD];
__device__ bf16 g_kh[MTOT*DD],  g_kl[MTOT*DD];
__device__ bf16 g_vh[MTOT*DD],  g_vl[MTOT*DD];
__device__ bf16 g_aoh[MTOT*DD], g_aol[MTOT*DD];
__device__ bf16 g_Wqh[DD*DD], g_Wql[DD*DD];
__device__ bf16 g_Wkh[DD*DD], g_Wkl[DD*DD];
__device__ bf16 g_Wvh[DD*DD], g_Wvl[DD*DD];
__device__ bf16 g_Woh[DD*DD], g_Wol[DD*DD];
__device__ bf16 g_wt0h[3*COUT*DD], g_wt0l[3*COUT*DD];   // [t][co][ci]
__device__ bf16 g_wt1h[5*COUT*DD], g_wt1l[5*COUT*DD];

// bf16 hi/lo, head layout [B,H,S,DH] (attention inputs)
__device__ bf16 g_qhh[BB*HH*SS*DHD], g_qhl[BB*HH*SS*DHD];   // Q PRE-SCALED by 0.125
__device__ bf16 g_kmh[BB*HH*SS*DHD], g_kml[BB*HH*SS*DHD];
__device__ bf16 g_vhh[BB*HH*SS*DHD], g_vhl[BB*HH*SS*DHD];

// packed mask bits: [B][S][S/32] words
__device__ unsigned int g_mbits[BB*SS*(SS/32)];

__device__ __forceinline__ float sigm(float x){ return 1.0f/(1.0f+__expf(-x)); }

__device__ __forceinline__ void split4(float4 f, uint2& hv, uint2& lv){
    float fv[4] = {f.x, f.y, f.z, f.w};
    unsigned int hw[4], lw[4];
    #pragma unroll
    for (int j=0;j<4;j++){
        bf16 h = __float2bfloat16(fv[j]);
        bf16 l = __float2bfloat16(fv[j] - __bfloat162float(h));
        hw[j] = (unsigned int)__bfloat16_as_ushort(h);
        lw[j] = (unsigned int)__bfloat16_as_ushort(l);
    }
    hv = make_uint2(hw[0] | (hw[1]<<16), hw[2] | (hw[3]<<16));
    lv = make_uint2(lw[0] | (lw[1]<<16), lw[2] | (lw[3]<<16));
}

// ---------------- ONE fused prep kernel ----------------------------------------
#define NBIG4 (MTOT*DD/4)
#define NBIG8 (NBIG4/2)
#define NW8   (DD*DD/8)

__global__ void prep_all(const float* __restrict__ q, const float* __restrict__ k,
                         const float* __restrict__ v,
                         const float* __restrict__ Wq, const float* __restrict__ Wk,
                         const float* __restrict__ Wv, const float* __restrict__ Wo,
                         const float* __restrict__ w0, const float* __restrict__ w1,
                         const int* __restrict__ mask){
    int bid = blockIdx.x;
    if (bid < 6144){
        int i = bid*256 + threadIdx.x;
        if (i >= 3*NBIG8) return;
        int sel = i / NBIG8, j = (i - sel*NBIG8)*2;
        const float4* s4; uint2 *hi, *lo;
        if (sel==0){ s4=(const float4*)q; hi=(uint2*)g_qh; lo=(uint2*)g_ql; }
        else if (sel==1){ s4=(const float4*)k; hi=(uint2*)g_kh; lo=(uint2*)g_kl; }
        else { s4=(const float4*)v; hi=(uint2*)g_vh; lo=(uint2*)g_vl; }
        float4 f0 = s4[j], f1 = s4[j+1];
        uint2 hv, lv;
        split4(f0, hv, lv); hi[j]=hv;   lo[j]=lv;
        split4(f1, hv, lv); hi[j+1]=hv; lo[j+1]=lv;
    } else if (bid < 8192){
        int i = (bid-6144)*256 + threadIdx.x;
        if (i >= 4*NW8) return;
        int sel = i / NW8, j = (i - sel*NW8)*2;
        const float4* s4; uint2 *hi, *lo;
        if (sel==0){ s4=(const float4*)Wq; hi=(uint2*)g_Wqh; lo=(uint2*)g_Wql; }
        else if (sel==1){ s4=(const float4*)Wk; hi=(uint2*)g_Wkh; lo=(uint2*)g_Wkl; }
        else if (sel==2){ s4=(const float4*)Wv; hi=(uint2*)g_Wvh; lo=(uint2*)g_Wvl; }
        else { s4=(const float4*)Wo; hi=(uint2*)g_Woh; lo=(uint2*)g_Wol; }
        float4 f0 = s4[j], f1 = s4[j+1];
        uint2 hv, lv;
        split4(f0, hv, lv); hi[j]=hv;   lo[j]=lv;
        split4(f1, hv, lv); hi[j+1]=hv; lo[j+1]=lv;
    } else if (bid < 18432){
        int idx = (bid-8192)*256 + threadIdx.x;
        const int tot0 = 3*COUT*DD;
        const int tot1 = 5*COUT*DD;
        if (idx < tot0){
            int t = idx/(COUT*DD); int r = idx%(COUT*DD);
            int co = r/DD, ci = r%DD;
            float vv = w0[(co*DD+ci)*3 + t];
            bf16 h = __float2bfloat16(vv);
            g_wt0h[idx] = h;
            g_wt0l[idx] = __float2bfloat16(vv - __bfloat162float(h));
        }
        if (idx < tot1){
            int t = idx/(COUT*DD); int r = idx%(COUT*DD);
            int co = r/DD, ci = r%DD;
            float vv = w1[(co*DD+ci)*5 + t];
            bf16 h = __float2bfloat16(vv);
            g_wt1h[idx] = h;
            g_wt1l[idx] = __float2bfloat16(vv - __bfloat162float(h));
        }
    } else {
        int i = (bid-18432)*256 + threadIdx.x;
        unsigned int b = __ballot_sync(0xffffffffu, mask[i] != 0);
        if ((threadIdx.x & 31) == 0) g_mbits[i >> 5] = b;
    }
}

// km = g_km + g_kc, split to head-layout hi/lo (2 float4/thread)
__global__ void cvt_km(int n8){
    int i0 = (blockIdx.x*blockDim.x + threadIdx.x);
    if (i0 >= n8) return;
    int j = i0*2;
    #pragma unroll
    for (int t=0;t<2;t++){
        float4 a = ((const float4*)g_km)[j+t];
        float4 b = ((const float4*)g_kc)[j+t];
        a.x += b.x; a.y += b.y; a.z += b.z; a.w += b.w;
        uint2 hv, lv; split4(a, hv, lv);
        ((uint2*)g_kmh)[j+t]=hv; ((uint2*)g_kml)[j+t]=lv;
    }
}

// ---------------- fused tensor-core bf16x3 GEMM (R9 proven: 8 warps, 32x64) -----
#define BKS 16
#define SST 24           // smem row stride in bf16 elems (16 data + 8 pad)
#define TILEE 3072       // one 128-row array: 128*SST elems
#define STGE 12288       // 4 arrays per stage (elems)
#define NSTG 3
#define SMEM_BYTES 73728 // 3 stages * 24576B

__device__ __forceinline__ void cp_stage_rt(int mode, bf16* smem, int slot, int k0,
                                            int m0, int n0, int tid){
    const bf16 *Ah, *Al, *Bh, *Bl;
    if (mode==0){ Ah=g_qh; Al=g_ql; Bh=g_Wqh; Bl=g_Wql; }
    else if (mode==1){ Ah=g_kh; Al=g_kl; Bh=g_Wkh; Bl=g_Wkl; }
    else if (mode==3){ Ah=g_vh; Al=g_vl; Bh=g_Wvh; Bl=g_Wvl; }
    else if (mode==4){ Ah=g_kh; Al=g_kl; Bh=g_wt0h; Bl=g_wt0l; }
    else { Ah=g_kh; Al=g_kl; Bh=g_wt1h; Bl=g_wt1l; }

    const int row = tid >> 1;
    const int cg  = (tid & 1)*8;
    bf16* pA = smem + slot*STGE + row*SST + cg;

    if (mode<=3){
        size_t off = (size_t)(m0+row)*DD + k0 + cg;
        __pipeline_memcpy_async(pA,         Ah+off, 16);
        __pipeline_memcpy_async(pA+TILEE,   Al+off, 16);
        size_t offb = (size_t)(n0+row)*DD + k0 + cg;
        __pipeline_memcpy_async(pA+2*TILEE, Bh+offb, 16);
        __pipeline_memcpy_async(pA+3*TILEE, Bl+offb, 16);
    } else {
        const int pad = (mode==4)?1:2;
        int t   = k0 >> 10;
        int ci0 = k0 & 1023;
        int m   = m0 + row;
        int bidx = m >> 11;
        int s2  = (m & 2047) + t - pad;
        bool ok = (s2 >= 0 && s2 < SS);
        size_t off = ok ? ((size_t)(bidx*SS + s2)*DD + ci0 + cg) : 0;
        size_t zf  = ok ? 0 : 16;
        __pipeline_memcpy_async(pA,         Ah+off, 16, zf);
        __pipeline_memcpy_async(pA+TILEE,   Al+off, 16, zf);
        size_t offb = ((size_t)t*COUT + (n0+row))*DD + ci0 + cg;
        __pipeline_memcpy_async(pA+2*TILEE, Bh+offb, 16);
        __pipeline_memcpy_async(pA+3*TILEE, Bl+offb, 16);
    }
}

__global__ __launch_bounds__(256,2) void mma_gemm_fused(
        const float* __restrict__ gate, const float* __restrict__ cb0,
        const float* __restrict__ cb1){
    extern __shared__ __align__(16) bf16 smem[];
    const int tid  = threadIdx.x;
    const int wid  = tid >> 5, lane = tid & 31;
    const int wm   = wid >> 1, wn = wid & 1;     // warp grid 4x2, warp tile 32x64

    int bid = blockIdx.x;
    int mode, r;
    if (bid < 128)      { mode=5; r=bid; }
    else if (bid < 256) { mode=4; r=bid-128; }
    else if (bid < 512) { mode=1; r=bid-256; }
    else if (bid < 768) { mode=0; r=bid-512; }
    else                { mode=3; r=bid-768; }
    int m0, n0;
    if (mode>=4){ n0=(r&3)*128; m0=(r>>2)*128; }
    else        { n0=(r&7)*128; m0=(r>>3)*128; }
    const int STEPS = (mode==5) ? 320 : (mode==4) ? 192 : 64;

    wmma::fragment<wmma::accumulator,16,16,16,float> facc[2][4];
    #pragma unroll
    for (int i=0;i<2;i++)
        #pragma unroll
        for (int j=0;j<4;j++) wmma::fill_fragment(facc[i][j], 0.0f);

    cp_stage_rt(mode, smem, 0, 0,   m0, n0, tid); __pipeline_commit();
    cp_stage_rt(mode, smem, 1, BKS, m0, n0, tid); __pipeline_commit();

    for (int s=0; s<STEPS; s++){
        __pipeline_wait_prior(1);
        __syncthreads();

        const bf16* sAh = smem + (s%NSTG)*STGE;
        const bf16* sAl = sAh + TILEE;
        const bf16* sBh = sAh + 2*TILEE;
        const bf16* sBl = sAh + 3*TILEE;

        wmma::fragment<wmma::matrix_a,16,16,16,bf16,wmma::row_major> fah[2], fal[2];
        #pragma unroll
        for (int i=0;i<2;i++){
            wmma::load_matrix_sync(fah[i], sAh + (wm*32 + i*16)*SST, SST);
            wmma::load_matrix_sync(fal[i], sAl + (wm*32 + i*16)*SST, SST);
        }
        #pragma unroll
        for (int j=0;j<4;j++){
            wmma::fragment<wmma::matrix_b,16,16,16,bf16,wmma::col_major> fbh, fbl;
            wmma::load_matrix_sync(fbh, sBh + (wn*64 + j*16)*SST, SST);
            wmma::load_matrix_sync(fbl, sBl + (wn*64 + j*16)*SST, SST);
            #pragma unroll
            for (int i=0;i<2;i++){
                wmma::mma_sync(facc[i][j], fah[i], fbh, facc[i][j]);
                wmma::mma_sync(facc[i][j], fah[i], fbl, facc[i][j]);
                wmma::mma_sync(facc[i][j], fal[i], fbh, facc[i][j]);
            }
        }
        if (s+2 < STEPS) cp_stage_rt(mode, smem, (s+2)%NSTG, (s+2)*BKS, m0, n0, tid);
        __pipeline_commit();
    }
    __syncthreads();

    // ---- epilogue: per-warp 1KB scratch chunks ----
    float* scr = (float*)smem + wid*256;   // 16x16 per warp
    #pragma unroll
    for (int i=0;i<2;i++){
        #pragma unroll
        for (int j=0;j<4;j++){
            wmma::store_matrix_sync(scr, facc[i][j], 16, wmma::mem_row_major);
            __syncwarp();
            #pragma unroll
            for (int t=0;t<8;t++){
                int e = lane + t*32;
                int row = e >> 4, col = e & 15;
                float val = scr[e];
                int gm = m0 + wm*32 + i*16 + row;
                int gn = n0 + wn*64 + j*16 + col;
                int bidx = gm>>11, ss2 = gm&2047;
                if (mode==0 || mode==3){
                    int hh2 = gn>>6, d = gn&63;
                    size_t idx = (((size_t)bidx*HH+hh2)*SS+ss2)*DHD + d;
                    if (mode==0) val *= 0.125f;   // fold attention scale into Q (exact)
                    bf16 hv = __float2bfloat16(val);
                    bf16 lv = __float2bfloat16(val - __bfloat162float(hv));
                    if (mode==0){ g_qhh[idx]=hv; g_qhl[idx]=lv; }
                    else        { g_vhh[idx]=hv; g_vhl[idx]=lv; }
                } else if (mode==1){
                    int hh2 = gn>>6, d = gn&63;
                    float sc = 1.0f - sigm(gate[hh2]);
                    g_km[(((size_t)bidx*HH+hh2)*SS+ss2)*DHD + d] = val*sc;
                } else {
                    const int branch = (mode==5) ? 1 : 0;
                    const float* bias = branch ? cb1 : cb0;
                    int gc = branch*COUT + gn;
                    int hh2 = gc>>6, d = gc&63;
                    float g = sigm(gate[hh2]);
                    g_kc[(((size_t)bidx*HH+hh2)*SS+ss2)*DHD + d] = g*(val + bias[gn]);
                }
            }
            __syncwarp();
        }
    }
}

// ---------------- out-projection GEMM (R9 proven shape) -------------------------
__device__ __forceinline__ void cp_out(bf16* smem, int slot, int k0,
                                       int m0, int n0, int tid){
    const int row = tid >> 1;
    const int cg  = (tid & 1)*8;
    bf16* pA = smem + slot*STGE + row*SST + cg;
    size_t off  = (size_t)(m0+row)*DD + k0 + cg;
    size_t offb = (size_t)(n0+row)*DD + k0 + cg;
    __pipeline_memcpy_async(pA,         g_aoh+off, 16);
    __pipeline_memcpy_async(pA+TILEE,   g_aol+off, 16);
    __pipeline_memcpy_async(pA+2*TILEE, g_Woh+offb, 16);
    __pipeline_memcpy_async(pA+3*TILEE, g_Wol+offb, 16);
}

__global__ __launch_bounds__(256,2) void mma_gemm_out(
        float* __restrict__ dstp, const float* __restrict__ bo){
    extern __shared__ __align__(16) bf16 smem[];
    const int tid  = threadIdx.x;
    const int wid  = tid >> 5, lane = tid & 31;
    const int wm   = wid >> 1, wn = wid & 1;
    const int m0   = blockIdx.y*128;
    const int n0   = blockIdx.x*128;
    const int STEPS = DD/BKS;

    wmma::fragment<wmma::accumulator,16,16,16,float> facc[2][4];
    #pragma unroll
    for (int i=0;i<2;i++)
        #pragma unroll
        for (int j=0;j<4;j++) wmma::fill_fragment(facc[i][j], 0.0f);

    cp_out(smem, 0, 0,   m0, n0, tid); __pipeline_commit();
    cp_out(smem, 1, BKS, m0, n0, tid); __pipeline_commit();

    for (int s=0; s<STEPS; s++){
        __pipeline_wait_prior(1);
        __syncthreads();

        const bf16* sAh = smem + (s%NSTG)*STGE;
        const bf16* sAl = sAh + TILEE;
        const bf16* sBh = sAh + 2*TILEE;
        const bf16* sBl = sAh + 3*TILEE;

        wmma::fragment<wmma::matrix_a,16,16,16,bf16,wmma::row_major> fah[2], fal[2];
        #pragma unroll
        for (int i=0;i<2;i++){
            wmma::load_matrix_sync(fah[i], sAh + (wm*32 + i*16)*SST, SST);
            wmma::load_matrix_sync(fal[i], sAl + (wm*32 + i*16)*SST, SST);
        }
        #pragma unroll
        for (int j=0;j<4;j++){
            wmma::fragment<wmma::matrix_b,16,16,16,bf16,wmma::col_major> fbh, fbl;
            wmma::load_matrix_sync(fbh, sBh + (wn*64 + j*16)*SST, SST);
            wmma::load_matrix_sync(fbl, sBl + (wn*64 + j*16)*SST, SST);
            #pragma unroll
            for (int i=0;i<2;i++){
                wmma::mma_sync(facc[i][j], fah[i], fbh, facc[i][j]);
                wmma::mma_sync(facc[i][j], fah[i], fbl, facc[i][j]);
                wmma::mma_sync(facc[i][j], fal[i], fbh, facc[i][j]);
            }
        }
        if (s+2 < STEPS) cp_out(smem, (s+2)%NSTG, (s+2)*BKS, m0, n0, tid);
        __pipeline_commit();
    }
    __syncthreads();

    float* scr = (float*)smem + wid*256;
    #pragma unroll
    for (int i=0;i<2;i++){
        #pragma unroll
        for (int j=0;j<4;j++){
            wmma::store_matrix_sync(scr, facc[i][j], 16, wmma::mem_row_major);
            __syncwarp();
            #pragma unroll
            for (int t=0;t<8;t++){
                int e = lane + t*32;
                int row2 = e >> 4, col = e & 15;
                int gm = m0 + wm*32 + i*16 + row2;
                int gn = n0 + wn*64 + j*16 + col;
                dstp[(size_t)gm*DD + gn] = scr[e] + bo[gn];
            }
            __syncwarp();
        }
    }
}

// ---------------- flash attention: FKT=32, 3-stage ring, 3 CTAs/SM --------------
// Q pre-scaled by 0.125; P stored hi/lo (precision-critical)
#define FQT 64
#define FKT 32
#define FST 72       // K/V bf16 row stride (64 data + 8 pad)
#define PST 40       // P row stride (32 data + 8 pad)
#define KVB 4608     // one 32x72 bf16 array in bytes
#define BUFBY 18432  // Kh,Kl,Vh,Vl per stage
#define FNSTG 3
#define O_P 55296    // after 3 KV stages: Ph (5120B) + Pl (5120B)
#define FSM 65536

__device__ __forceinline__ void cp_kv(unsigned char* fsm, int slot, size_t base,
                                      int k0, int tid){
    #pragma unroll
    for (int i=0;i<8;i++){
        int idx = tid + i*128;
        int arr = idx >> 8, e = idx & 255;
        int row = e >> 3, c = (e & 7)*8;
        const bf16* src = g_kmh;
        if (arr==1) src = g_kml;
        if (arr==2) src = g_vhh;
        if (arr==3) src = g_vhl;
        __pipeline_memcpy_async((bf16*)(fsm + slot*BUFBY + arr*KVB) + row*FST + c,
                                src + base + (size_t)(k0+row)*DHD + c, 16);
    }
}
__device__ __forceinline__ void st_pair(bf16* hp, bf16* lp, int off, float a, float b){
    bf16 ha = __float2bfloat16(a);
    bf16 hb = __float2bfloat16(b);
    __nv_bfloat162 hv; hv.x = ha; hv.y = hb;
    __nv_bfloat162 lv;
    lv.x = __float2bfloat16(a - __bfloat162float(ha));
    lv.y = __float2bfloat16(b - __bfloat162float(hb));
    *(__nv_bfloat162*)(hp + off) = hv;
    *(__nv_bfloat162*)(lp + off) = lv;
}

__global__ __launch_bounds__(128,3) void flash_wmma(int dummy){
    extern __shared__ __align__(16) unsigned char fsm[];
    const int tid = threadIdx.x;
    const int w = tid >> 5, lane = tid & 31;
    const int bh = blockIdx.y;
    const int b = bh >> 4, h = bh & 15;
    const int q0 = blockIdx.x*FQT;
    const size_t base = (size_t)bh*SS*DHD;
    const int NI = SS/FKT;   // 64

    bf16* Ph = (bf16*)(fsm + O_P);
    bf16* Pl = (bf16*)(fsm + O_P + 5120);

    // stage Q tile (64x64 hi/lo) into the KV buffer region (pre-loop only)
    bf16* Qsh = (bf16*)fsm;
    bf16* Qsl = (bf16*)(fsm + 9216);
    #pragma unroll
    for (int i=0;i<4;i++){
        int idx = tid + i*128;
        int row = idx >> 3, c = (idx & 7)*8;
        *(uint4*)(Qsh + row*FST + c) = *(const uint4*)(g_qhh + base + (size_t)(q0+row)*DHD + c);
        *(uint4*)(Qsl + row*FST + c) = *(const uint4*)(g_qhl + base + (size_t)(q0+row)*DHD + c);
    }
    __syncthreads();

    wmma::fragment<wmma::matrix_a,16,16,16,bf16,wmma::row_major> qah[4], qal[4];
    #pragma unroll
    for (int kk=0;kk<4;kk++){
        wmma::load_matrix_sync(qah[kk], Qsh + (w*16)*FST + kk*16, FST);
        wmma::load_matrix_sync(qal[kk], Qsl + (w*16)*FST + kk*16, FST);
    }
    __syncthreads();   // Q in regs before KV buffers are overwritten

    cp_kv(fsm, 0, base, 0,   tid); __pipeline_commit();
    cp_kv(fsm, 1, base, FKT, tid); __pipeline_commit();

    wmma::fragment<wmma::accumulator,16,16,16,float> oacc[4];
    #pragma unroll
    for (int j=0;j<4;j++) wmma::fill_fragment(oacc[j], 0.0f);

    const int r0 = lane >> 2;
    const int grow0 = q0 + w*16 + r0;
    float mr0 = -CUDART_INF_F, mr1 = -CUDART_INF_F;
    float l0 = 0.0f, l1 = 0.0f;

    int cur = 0;
    for (int kb=0; kb<NI; kb++){
        __pipeline_wait_prior(1);
        __syncthreads();

        bf16* Kh = (bf16*)(fsm + cur*BUFBY);
        bf16* Kl = (bf16*)(fsm + cur*BUFBY + KVB);
        bf16* Vh = (bf16*)(fsm + cur*BUFBY + 2*KVB);
        bf16* Vl = (bf16*)(fsm + cur*BUFBY + 3*KVB);

        wmma::fragment<wmma::accumulator,16,16,16,float> sacc[2];
        #pragma unroll
        for (int j=0;j<2;j++) wmma::fill_fragment(sacc[j], 0.0f);

        #pragma unroll
        for (int kk=0;kk<4;kk++){
            #pragma unroll
            for (int j=0;j<2;j++){
                wmma::fragment<wmma::matrix_b,16,16,16,bf16,wmma::col_major> kbh, kbl;
                wmma::load_matrix_sync(kbh, Kh + (j*16)*FST + kk*16, FST);
                wmma::load_matrix_sync(kbl, Kl + (j*16)*FST + kk*16, FST);
                wmma::mma_sync(sacc[j], qah[kk], kbh, sacc[j]);
                wmma::mma_sync(sacc[j], qah[kk], kbl, sacc[j]);
                wmma::mma_sync(sacc[j], qal[kk], kbh, sacc[j]);
            }
        }

        // scores arrive pre-scaled. Mask: fast path when fully set.
        unsigned int mb0 = g_mbits[((size_t)b*SS + grow0)*(SS/32) + kb];
        unsigned int mb1 = g_mbits[((size_t)b*SS + grow0 + 8)*(SS/32) + kb];
        if ((mb0 & mb1) != 0xFFFFFFFFu){
            #pragma unroll
            for (int j=0;j<2;j++){
                float* x = sacc[j].x;
                int c0 = j*16 + (lane&3)*2;
                if (!((mb0 >> c0)     & 1)) x[0] = -1e9f;
                if (!((mb0 >> (c0+1)) & 1)) x[1] = -1e9f;
                if (!((mb0 >> (c0+8)) & 1)) x[4] = -1e9f;
                if (!((mb0 >> (c0+9)) & 1)) x[5] = -1e9f;
                if (!((mb1 >> c0)     & 1)) x[2] = -1e9f;
                if (!((mb1 >> (c0+1)) & 1)) x[3] = -1e9f;
                if (!((mb1 >> (c0+8)) & 1)) x[6] = -1e9f;
                if (!((mb1 >> (c0+9)) & 1)) x[7] = -1e9f;
            }
        }

        float rm0 = -CUDART_INF_F, rm1 = -CUDART_INF_F;
        #pragma unroll
        for (int j=0;j<2;j++){
            float* x = sacc[j].x;
            rm0 = fmaxf(rm0, fmaxf(fmaxf(x[0],x[1]), fmaxf(x[4],x[5])));
            rm1 = fmaxf(rm1, fmaxf(fmaxf(x[2],x[3]), fmaxf(x[6],x[7])));
        }
        rm0 = fmaxf(rm0, __shfl_xor_sync(0xffffffffu, rm0, 1));
        rm0 = fmaxf(rm0, __shfl_xor_sync(0xffffffffu, rm0, 2));
        rm1 = fmaxf(rm1, __shfl_xor_sync(0xffffffffu, rm1, 1));
        rm1 = fmaxf(rm1, __shfl_xor_sync(0xffffffffu, rm1, 2));

        float mn0 = fmaxf(mr0, rm0), mn1 = fmaxf(mr1, rm1);
        float cr0 = __expf(mr0 - mn0), cr1 = __expf(mr1 - mn1);

        float ps0 = 0.0f, ps1 = 0.0f;
        const int lr0 = w*16 + r0;
        #pragma unroll
        for (int j=0;j<2;j++){
            float* x = sacc[j].x;
            int c0 = j*16 + (lane&3)*2;
            float p00 = __expf(x[0]-mn0), p01 = __expf(x[1]-mn0);
            float p08 = __expf(x[4]-mn0), p09 = __expf(x[5]-mn0);
            float p10 = __expf(x[2]-mn1), p11 = __expf(x[3]-mn1);
            float p18 = __expf(x[6]-mn1), p19 = __expf(x[7]-mn1);
            ps0 += (p00+p01) + (p08+p09);
            ps1 += (p10+p11) + (p18+p19);
            st_pair(Ph, Pl, lr0*PST + c0,       p00, p01);
            st_pair(Ph, Pl, lr0*PST + c0 + 8,   p08, p09);
            st_pair(Ph, Pl, (lr0+8)*PST + c0,   p10, p11);
            st_pair(Ph, Pl, (lr0+8)*PST + c0+8, p18, p19);
        }
        ps0 += __shfl_xor_sync(0xffffffffu, ps0, 1);
        ps0 += __shfl_xor_sync(0xffffffffu, ps0, 2);
        ps1 += __shfl_xor_sync(0xffffffffu, ps1, 1);
        ps1 += __shfl_xor_sync(0xffffffffu, ps1, 2);

        l0 = l0*cr0 + ps0;  l1 = l1*cr1 + ps1;
        mr0 = mn0;          mr1 = mn1;

        #pragma unroll
        for (int j=0;j<4;j++){
            float* x = oacc[j].x;
            x[0]*=cr0; x[1]*=cr0; x[4]*=cr0; x[5]*=cr0;
            x[2]*=cr1; x[3]*=cr1; x[6]*=cr1; x[7]*=cr1;
        }
        __syncwarp();

        #pragma unroll
        for (int kk=0;kk<2;kk++){
            wmma::fragment<wmma::matrix_a,16,16,16,bf16,wmma::row_major> pah, pal;
            wmma::load_matrix_sync(pah, Ph + (w*16)*PST + kk*16, PST);
            wmma::load_matrix_sync(pal, Pl + (w*16)*PST + kk*16, PST);
            #pragma unroll
            for (int j=0;j<4;j++){
                wmma::fragment<wmma::matrix_b,16,16,16,bf16,wmma::row_major> vbh, vbl;
                wmma::load_matrix_sync(vbh, Vh + (kk*16)*FST + j*16, FST);
                wmma::load_matrix_sync(vbl, Vl + (kk*16)*FST + j*16, FST);
                wmma::mma_sync(oacc[j], pah, vbh, oacc[j]);
                wmma::mma_sync(oacc[j], pah, vbl, oacc[j]);
                wmma::mma_sync(oacc[j], pal, vbh, oacc[j]);
            }
        }

        // 3-stage ring: prefetch target (kb+2)%3 was last read at kb-1, whose
        // reads completed before this iteration's top barrier -> no extra sync.
        if (kb+2 < NI){
            int nslot = cur+2; if (nslot >= FNSTG) nslot -= FNSTG;
            cp_kv(fsm, nslot, base, (kb+2)*FKT, tid);
        }
        __pipeline_commit();
        cur++; if (cur == FNSTG) cur = 0;
    }

    float inv0 = 1.0f / l0, inv1 = 1.0f / l1;
    int gr0 = q0 + w*16 + r0, gr1 = gr0 + 8;
    size_t ro0 = ((size_t)b*SS + gr0)*DD + h*DHD;
    size_t ro1 = ((size_t)b*SS + gr1)*DD + h*DHD;
    #pragma unroll
    for (int j=0;j<4;j++){
        float* x = oacc[j].x;
        int c0 = j*16 + (lane&3)*2;
        st_pair(g_aoh + ro0, g_aol + ro0, c0,     x[0]*inv0, x[1]*inv0);
        st_pair(g_aoh + ro0, g_aol + ro0, c0 + 8, x[4]*inv0, x[5]*inv0);
        st_pair(g_aoh + ro1, g_aol + ro1, c0,     x[2]*inv1, x[3]*inv1);
        st_pair(g_aoh + ro1, g_aol + ro1, c0 + 8, x[6]*inv1, x[7]*inv1);
    }
}

// ---------------- launch ------------------------------------------------------
extern "C" void kernel_launch(void* const* d_in, const int* in_sizes, int n_in,
                              void* d_out, int out_size){
    const float* q    = (const float*)d_in[0];
    const float* k    = (const float*)d_in[1];
    const float* v    = (const float*)d_in[2];
    const int*   mask = (const int*)  d_in[3];
    const float* Wq   = (const float*)d_in[4];
    const float* Wk   = (const float*)d_in[5];
    const float* Wv   = (const float*)d_in[6];
    const float* Wo   = (const float*)d_in[7];
    const float* bo   = (const float*)d_in[8];
    const float* cw0  = (const float*)d_in[9];
    const float* cb0  = (const float*)d_in[10];
    const float* cw1  = (const float*)d_in[11];
    const float* cb1  = (const float*)d_in[12];
    const float* gate = (const float*)d_in[13];
    float* out = (float*)d_out;

    prep_all<<<51200,256>>>(q, k, v, Wq, Wk, Wv, Wo, cw0, cw1, mask);

    cudaFuncSetAttribute(mma_gemm_fused, cudaFuncAttributeMaxDynamicSharedMemorySize, SMEM_BYTES);
    cudaFuncSetAttribute(mma_gemm_out,   cudaFuncAttributeMaxDynamicSharedMemorySize, SMEM_BYTES);
    cudaFuncSetAttribute(flash_wmma,     cudaFuncAttributeMaxDynamicSharedMemorySize, FSM);

    mma_gemm_fused<<<1024,256,SMEM_BYTES>>>(gate, cb0, cb1);

    cvt_km<<<(NBIG8+255)/256,256>>>(NBIG8);   // (g_km + g_kc) -> kmh/kml

    flash_wmma<<<dim3(SS/FQT, BB*HH), 128, FSM>>>(0);

    mma_gemm_out<<<dim3(DD/128, MTOT/128),256,SMEM_BYTES>>>(out, bo);
}